// round 5
// baseline (speedup 1.0000x reference)
#include <cuda_runtime.h>
#include <cstdint>
#include <cstddef>

// Problem constants (fixed by the reference)
#define NN    50000
#define HH    128
#define TT    4
#define EE    150000
#define K4    512      // T*H
#define SEGS  (NN*TT)

// ---------------------------------------------------------------------------
// Scratch (no allocations allowed -> __device__ globals)
// ---------------------------------------------------------------------------
__device__ float g_h   [(size_t)NN * HH];
__device__ float g_S   [(size_t)NN * K4];
__device__ float g_inc [(size_t)NN * HH];
__device__ float g_Wcat[2 * HH * K4];
__device__ float g_Wc0 [512 * 256];     // combined gate weights, layer 0
__device__ float g_Wc1 [512 * 384];     // combined gate weights, layer 1
__device__ float g_b0  [512];
__device__ float g_b1  [512];
__device__ int   g_cnt [SEGS];
__device__ int   g_off [SEGS + 1];
__device__ int   g_cur [SEGS];
__device__ int   g_csr [TT * EE];

// ---------------------------------------------------------------------------
// CSR build (edges identical across timesteps -> once per launch)
// ---------------------------------------------------------------------------
__global__ void count_kernel(const int* __restrict__ edges)
{
    int idx = blockIdx.x * blockDim.x + threadIdx.x;
    if (idx >= TT * EE) return;
    int t   = idx / EE;
    int tgt = edges[(size_t)idx * 2 + 1];
    atomicAdd(&g_cnt[tgt * TT + t], 1);
}

__global__ void scan_kernel()
{
    __shared__ int s[1024];
    const int n     = SEGS;
    const int chunk = (n + 1023) / 1024;
    int tid = threadIdx.x;
    int lo  = tid * chunk;
    int hi  = min(lo + chunk, n);

    int sum = 0;
    for (int i = lo; i < hi; ++i) sum += g_cnt[i];
    s[tid] = sum;
    __syncthreads();
    for (int o = 1; o < 1024; o <<= 1) {
        int v = (tid >= o) ? s[tid - o] : 0;
        __syncthreads();
        s[tid] += v;
        __syncthreads();
    }
    int run = (tid == 0) ? 0 : s[tid - 1];
    for (int i = lo; i < hi; ++i) { g_off[i] = run; run += g_cnt[i]; }
    if (tid == 1023) g_off[n] = s[1023];
}

__global__ void fill_kernel(const int* __restrict__ edges)
{
    int idx = blockIdx.x * blockDim.x + threadIdx.x;
    if (idx >= TT * EE) return;
    int t   = idx / EE;
    int src = edges[(size_t)idx * 2 + 0];
    int tgt = edges[(size_t)idx * 2 + 1];
    int seg = tgt * TT + t;
    int pos = atomicAdd(&g_cur[seg], 1);
    g_csr[pos] = src;
}

// Rearrange msg_W (L,T,H,H) -> Wcat[l][f][t*128+k]
__global__ void wcat_kernel(const float* __restrict__ msg_W)
{
    int idx = blockIdx.x * blockDim.x + threadIdx.x;
    if (idx >= 2 * HH * K4) return;
    int l  = idx / (HH * K4);
    int r  = idx % (HH * K4);
    int f  = r / K4;
    int kk = r % K4;
    int t  = kk >> 7;
    int k  = kk & 127;
    g_Wcat[idx] = msg_W[(((size_t)l * TT + t) * HH + f) * HH + k];
}

// Combined gate weights, layer 0: Wc0[j][k], j in [0,512), k in [0,256)
//   j<256   (r,z summed): k<128 -> Wih[j][k], else Whh[j][k-128]
//   256..384 (xn):        k<128 -> Wih[j][k], else 0
//   384..512 (hn):        k<128 -> 0, else Whh[j-128][k-128]
__global__ void build_comb0(const float* __restrict__ Wih, const float* __restrict__ Whh,
                            const float* __restrict__ bih, const float* __restrict__ bhh)
{
    int idx = blockIdx.x * blockDim.x + threadIdx.x;
    if (idx >= 512 * 256) return;
    int j = idx >> 8;
    int k = idx & 255;
    float v = 0.f;
    if (j < 256)      v = (k < 128) ? Wih[j * 128 + k] : Whh[j * 128 + (k - 128)];
    else if (j < 384) { if (k < 128) v = Wih[j * 128 + k]; }
    else              { if (k >= 128) v = Whh[(j - 128) * 128 + (k - 128)]; }
    g_Wc0[idx] = v;
    if (idx < 512) {
        float b;
        if (idx < 256)      b = bih[idx] + bhh[idx];
        else if (idx < 384) b = bih[idx];
        else                b = bhh[idx - 128];
        g_b0[idx] = b;
    }
}

// Combined gate weights, layer 1: Wc1[j][k], k in [0,384); A = [x|inc|h]
__global__ void build_comb1(const float* __restrict__ Wih, const float* __restrict__ Whh,
                            const float* __restrict__ bih, const float* __restrict__ bhh)
{
    int idx = blockIdx.x * blockDim.x + threadIdx.x;
    if (idx >= 512 * 384) return;
    int j = idx / 384;
    int k = idx % 384;
    float v = 0.f;
    if (j < 256)      v = (k < 256) ? Wih[j * 256 + k] : Whh[j * 128 + (k - 256)];
    else if (j < 384) { if (k < 256) v = Wih[j * 256 + k]; }
    else              { if (k >= 256) v = Whh[(j - 128) * 128 + (k - 256)]; }
    g_Wc1[idx] = v;
    if (idx < 512) {
        float b;
        if (idx < 256)      b = bih[idx] + bhh[idx];
        else if (idx < 384) b = bih[idx];
        else                b = bhh[idx - 128];
        g_b1[idx] = b;
    }
}

// ---------------------------------------------------------------------------
// Aggregation: S[n, t*128+f] = sum over incoming type-t edges of h[src][f]
// ---------------------------------------------------------------------------
__global__ void __launch_bounds__(128)
agg_kernel(const float* __restrict__ h)
{
    int n = blockIdx.x;
    int f = threadIdx.x;
    #pragma unroll
    for (int t = 0; t < TT; ++t) {
        int b = g_off[n * TT + t];
        int e = g_off[n * TT + t + 1];
        float a = 0.f;
        for (int i = b; i < e; ++i)
            a += __ldg(&h[(size_t)g_csr[i] * HH + f]);
        g_S[(size_t)n * K4 + t * HH + f] = a;
    }
}

// ---------------------------------------------------------------------------
// tf32 helpers
// ---------------------------------------------------------------------------
__device__ __forceinline__ float to_tf32(float x)
{
    uint32_t u;
    asm("cvt.rna.tf32.f32 %0, %1;" : "=r"(u) : "f"(x));
    return __uint_as_float(u);
}

__device__ __forceinline__ void mma_tf32(float* c, const uint32_t* a, const uint32_t* b)
{
    asm volatile(
        "mma.sync.aligned.m16n8k8.row.col.f32.tf32.tf32.f32 "
        "{%0,%1,%2,%3}, {%4,%5,%6,%7}, {%8,%9}, {%0,%1,%2,%3};"
        : "+f"(c[0]), "+f"(c[1]), "+f"(c[2]), "+f"(c[3])
        : "r"(a[0]), "r"(a[1]), "r"(a[2]), "r"(a[3]),
          "r"(b[0]), "r"(b[1]));
}

// ---------------------------------------------------------------------------
// inc GEMM (tensor cores): inc[m,f] = sum_kk S[m,kk]*Wcat[f,kk] + sum_t deg_t*b
// 128x128 tile, BK=32, 256 threads (8 warps: 4x2 of 32x64)
// ---------------------------------------------------------------------------
#define SSTR 36

__global__ void __launch_bounds__(256)
gemm_inc(const float* __restrict__ S,
         const float* __restrict__ Wc,     // [128][512]
         const float* __restrict__ bl,     // (T,H)
         float* __restrict__ inc)
{
    __shared__ float As[128 * SSTR];
    __shared__ float Bs[128 * SSTR];
    __shared__ float sb[512];

    const int tid  = threadIdx.x;
    const int lane = tid & 31;
    const int warp = tid >> 5;
    const int wm   = warp & 3;
    const int wn   = warp >> 2;
    const int row0 = blockIdx.x * 128;

    for (int i = tid; i < 512; i += 256) sb[i] = bl[i];

    float acc[2][8][4];
    #pragma unroll
    for (int mi = 0; mi < 2; ++mi)
        #pragma unroll
        for (int ni = 0; ni < 8; ++ni)
            #pragma unroll
            for (int q = 0; q < 4; ++q) acc[mi][ni][q] = 0.f;

    const int gr = lane >> 2;
    const int gc = lane & 3;

    for (int kt = 0; kt < K4; kt += 32) {
        #pragma unroll
        for (int i = 0; i < 4; ++i) {
            int idx = tid + i * 256;
            int r   = idx >> 3;
            int c   = (idx & 7) << 2;
            float4 v = make_float4(0.f, 0.f, 0.f, 0.f);
            if (row0 + r < NN)
                v = *reinterpret_cast<const float4*>(S + (size_t)(row0 + r) * K4 + kt + c);
            v.x = to_tf32(v.x); v.y = to_tf32(v.y);
            v.z = to_tf32(v.z); v.w = to_tf32(v.w);
            *reinterpret_cast<float4*>(As + r * SSTR + c) = v;

            float4 w = *reinterpret_cast<const float4*>(Wc + (size_t)r * K4 + kt + c);
            w.x = to_tf32(w.x); w.y = to_tf32(w.y);
            w.z = to_tf32(w.z); w.w = to_tf32(w.w);
            *reinterpret_cast<float4*>(Bs + r * SSTR + c) = w;
        }
        __syncthreads();

        #pragma unroll
        for (int kq = 0; kq < 4; ++kq) {
            const int kk = kq * 8;
            uint32_t a[2][4];
            #pragma unroll
            for (int mi = 0; mi < 2; ++mi) {
                int am = wm * 32 + mi * 16;
                a[mi][0] = __float_as_uint(As[(am + gr)     * SSTR + kk + gc]);
                a[mi][1] = __float_as_uint(As[(am + gr + 8) * SSTR + kk + gc]);
                a[mi][2] = __float_as_uint(As[(am + gr)     * SSTR + kk + gc + 4]);
                a[mi][3] = __float_as_uint(As[(am + gr + 8) * SSTR + kk + gc + 4]);
            }
            #pragma unroll
            for (int ni = 0; ni < 8; ++ni) {
                int bn = wn * 64 + ni * 8;
                uint32_t b[2];
                b[0] = __float_as_uint(Bs[(bn + gr) * SSTR + kk + gc]);
                b[1] = __float_as_uint(Bs[(bn + gr) * SSTR + kk + gc + 4]);
                mma_tf32(acc[0][ni], a[0], b);
                mma_tf32(acc[1][ni], a[1], b);
            }
        }
        __syncthreads();
    }

    #pragma unroll
    for (int mi = 0; mi < 2; ++mi) {
        const int rbase = row0 + wm * 32 + mi * 16 + gr;
        float dg[2][4];
        #pragma unroll
        for (int hh = 0; hh < 2; ++hh) {
            int r = rbase + hh * 8;
            if (r < NN) {
                int o0 = g_off[r*4+0], o1 = g_off[r*4+1], o2 = g_off[r*4+2];
                int o3 = g_off[r*4+3], o4 = g_off[r*4+4];
                dg[hh][0] = (float)(o1 - o0); dg[hh][1] = (float)(o2 - o1);
                dg[hh][2] = (float)(o3 - o2); dg[hh][3] = (float)(o4 - o3);
            }
        }
        #pragma unroll
        for (int ni = 0; ni < 8; ++ni) {
            const int f = wn * 64 + ni * 8 + gc * 2;
            #pragma unroll
            for (int hh = 0; hh < 2; ++hh) {
                int r = rbase + hh * 8;
                if (r < NN) {
                    float v0 = acc[mi][ni][hh * 2 + 0];
                    float v1 = acc[mi][ni][hh * 2 + 1];
                    v0 += dg[hh][0]*sb[f]     + dg[hh][1]*sb[128+f]
                        + dg[hh][2]*sb[256+f] + dg[hh][3]*sb[384+f];
                    v1 += dg[hh][0]*sb[f+1]     + dg[hh][1]*sb[128+f+1]
                        + dg[hh][2]*sb[256+f+1] + dg[hh][3]*sb[384+f+1];
                    *reinterpret_cast<float2*>(inc + (size_t)r * HH + f) = make_float2(v0, v1);
                }
            }
        }
    }
}

// ---------------------------------------------------------------------------
// Fused gate GEMM + GRU update.
//   A = [A0 | A1 | A2] (each 128 K-cols), KA in {256, 384}
//   Gates: cols 0..255 = r,z (xr+hr / xz+hz summed), 256..383 = xn, 384..511 = hn
//   Epilogue: GRU, writes h in place (block's A rows == its C rows -> no race)
// Tile: 64 rows x 512 cols, BK=16, 256 threads, 8 warps.
// Warp w owns all 64 rows x cols {g*128 + w*16 + 0..15 : g in 0..3}
// ---------------------------------------------------------------------------
#define FSTR 20

template<int KA>
__global__ void __launch_bounds__(256)
fused_step(const float* __restrict__ A0,
           const float* __restrict__ A1,
           const float* __restrict__ A2,
           const float* __restrict__ Wc,    // [512][KA]
           const float* __restrict__ bias,  // [512]
           float* __restrict__ h)
{
    __shared__ float As[64 * FSTR];
    __shared__ float Bs[512 * FSTR];
    __shared__ float sb[512];

    const int tid  = threadIdx.x;
    const int lane = tid & 31;
    const int wrp  = tid >> 5;      // 0..7 -> 16-col slice within each gate group
    const int gr   = lane >> 2;
    const int gc   = lane & 3;
    const int row0 = blockIdx.x * 64;

    for (int i = tid; i < 512; i += 256) sb[i] = bias[i];

    float acc[4][8][4];
    #pragma unroll
    for (int mi = 0; mi < 4; ++mi)
        #pragma unroll
        for (int ni = 0; ni < 8; ++ni)
            #pragma unroll
            for (int q = 0; q < 4; ++q) acc[mi][ni][q] = 0.f;

    for (int kt = 0; kt < KA; kt += 16) {
        const float* Ap = (kt < 128) ? A0 : ((kt < 256) ? A1 : A2);
        const int klocal = kt & 127;
        // A tile: 64 rows x 16 k = 256 float4, 1/thread
        {
            int r  = tid >> 2;
            int c4 = (tid & 3) << 2;
            float4 v = make_float4(0.f, 0.f, 0.f, 0.f);
            if (row0 + r < NN)
                v = *reinterpret_cast<const float4*>(Ap + (size_t)(row0 + r) * HH + klocal + c4);
            v.x = to_tf32(v.x); v.y = to_tf32(v.y);
            v.z = to_tf32(v.z); v.w = to_tf32(v.w);
            *reinterpret_cast<float4*>(As + r * FSTR + c4) = v;
        }
        // B tile: 512 rows x 16 k = 2048 float4, 8/thread
        #pragma unroll
        for (int i = 0; i < 8; ++i) {
            int idx = tid + i * 256;
            int r   = idx >> 2;
            int c4  = (idx & 3) << 2;
            float4 w = *reinterpret_cast<const float4*>(Wc + (size_t)r * KA + kt + c4);
            w.x = to_tf32(w.x); w.y = to_tf32(w.y);
            w.z = to_tf32(w.z); w.w = to_tf32(w.w);
            *reinterpret_cast<float4*>(Bs + r * FSTR + c4) = w;
        }
        __syncthreads();

        #pragma unroll
        for (int kq = 0; kq < 2; ++kq) {
            const int kk = kq * 8;
            uint32_t a[4][4];
            #pragma unroll
            for (int mi = 0; mi < 4; ++mi) {
                int am = mi * 16;
                a[mi][0] = __float_as_uint(As[(am + gr)     * FSTR + kk + gc]);
                a[mi][1] = __float_as_uint(As[(am + gr + 8) * FSTR + kk + gc]);
                a[mi][2] = __float_as_uint(As[(am + gr)     * FSTR + kk + gc + 4]);
                a[mi][3] = __float_as_uint(As[(am + gr + 8) * FSTR + kk + gc + 4]);
            }
            #pragma unroll
            for (int ni = 0; ni < 8; ++ni) {
                int col = (ni >> 1) * 128 + wrp * 16 + (ni & 1) * 8;
                uint32_t b[2];
                b[0] = __float_as_uint(Bs[(col + gr) * FSTR + kk + gc]);
                b[1] = __float_as_uint(Bs[(col + gr) * FSTR + kk + gc + 4]);
                #pragma unroll
                for (int mi = 0; mi < 4; ++mi)
                    mma_tf32(acc[mi][ni], a[mi], b);
            }
        }
        __syncthreads();
    }

    // ---- GRU epilogue: each thread has matching (r,z,xn,hn) in its accs ----
    #pragma unroll
    for (int mi = 0; mi < 4; ++mi) {
        #pragma unroll
        for (int nlo = 0; nlo < 2; ++nlo) {
            #pragma unroll
            for (int q = 0; q < 4; ++q) {
                int row = row0 + mi * 16 + gr + (q >> 1) * 8;
                int f   = wrp * 16 + nlo * 8 + gc * 2 + (q & 1);
                if (row < NN) {
                    float rv = acc[mi][0 + nlo][q] + sb[f];
                    float zv = acc[mi][2 + nlo][q] + sb[128 + f];
                    float xn = acc[mi][4 + nlo][q] + sb[256 + f];
                    float hn = acc[mi][6 + nlo][q] + sb[384 + f];
                    float r  = 1.0f / (1.0f + expf(-rv));
                    float z  = 1.0f / (1.0f + expf(-zv));
                    float nv = tanhf(xn + r * hn);
                    size_t off = (size_t)row * HH + f;
                    float hv = h[off];
                    h[off] = (1.0f - z) * nv + z * hv;
                }
            }
        }
    }
}

// ---------------------------------------------------------------------------
// Launch
// ---------------------------------------------------------------------------
extern "C" void kernel_launch(void* const* d_in, const int* in_sizes, int n_in,
                              void* d_out, int out_size)
{
    const float* x        = (const float*)d_in[0];
    const int*   edges    = (const int*)  d_in[1];
    const float* msg_W    = (const float*)d_in[2];
    const float* msg_b    = (const float*)d_in[3];
    const float* g0_Wih   = (const float*)d_in[4];
    const float* g0_Whh   = (const float*)d_in[5];
    const float* g0_bih   = (const float*)d_in[6];
    const float* g0_bhh   = (const float*)d_in[7];
    const float* g1_Wih   = (const float*)d_in[8];
    const float* g1_Whh   = (const float*)d_in[9];
    const float* g1_bih   = (const float*)d_in[10];
    const float* g1_bhh   = (const float*)d_in[11];

    float *h_, *S_, *inc_, *Wcat_, *Wc0_, *Wc1_, *b0_, *b1_;
    int *cnt_, *off_, *cur_;
    cudaGetSymbolAddress((void**)&h_,    g_h);
    cudaGetSymbolAddress((void**)&S_,    g_S);
    cudaGetSymbolAddress((void**)&inc_,  g_inc);
    cudaGetSymbolAddress((void**)&Wcat_, g_Wcat);
    cudaGetSymbolAddress((void**)&Wc0_,  g_Wc0);
    cudaGetSymbolAddress((void**)&Wc1_,  g_Wc1);
    cudaGetSymbolAddress((void**)&b0_,   g_b0);
    cudaGetSymbolAddress((void**)&b1_,   g_b1);
    cudaGetSymbolAddress((void**)&cnt_,  g_cnt);
    cudaGetSymbolAddress((void**)&off_,  g_off);
    cudaGetSymbolAddress((void**)&cur_,  g_cur);

    const size_t hbytes = (size_t)NN * HH * sizeof(float);

    cudaMemcpyAsync(h_, x, hbytes, cudaMemcpyDeviceToDevice);

    // --- CSR build ---
    cudaMemsetAsync(cnt_, 0, SEGS * sizeof(int));
    count_kernel<<<(TT*EE + 255)/256, 256>>>(edges);
    scan_kernel<<<1, 1024>>>();
    cudaMemcpyAsync(cur_, off_, SEGS * sizeof(int), cudaMemcpyDeviceToDevice);
    fill_kernel<<<(TT*EE + 255)/256, 256>>>(edges);

    // --- Weight prep ---
    wcat_kernel<<<(2*HH*K4 + 255)/256, 256>>>(msg_W);
    build_comb0<<<(512*256 + 255)/256, 256>>>(g0_Wih, g0_Whh, g0_bih, g0_bhh);
    build_comb1<<<(512*384 + 255)/256, 256>>>(g1_Wih, g1_Whh, g1_bih, g1_bhh);

    const dim3 inc_grid((NN + 127)/128, 1);
    const int  fs_grid = (NN + 63)/64;

    // ---- Layer 0: 3 timesteps ----
    for (int s = 0; s < 3; ++s) {
        agg_kernel<<<NN, HH>>>(h_);
        gemm_inc<<<inc_grid, 256>>>(S_, Wcat_ + 0*HH*K4, msg_b + (size_t)0*TT*HH, inc_);
        fused_step<256><<<fs_grid, 256>>>(inc_, h_, nullptr, Wc0_, b0_, h_);
    }

    // ---- Layer 1: 3 timesteps ----
    for (int s = 0; s < 3; ++s) {
        agg_kernel<<<NN, HH>>>(h_);
        gemm_inc<<<inc_grid, 256>>>(S_, Wcat_ + 1*HH*K4, msg_b + (size_t)1*TT*HH, inc_);
        fused_step<384><<<fs_grid, 256>>>(x, inc_, h_, Wc1_, b1_, h_);
    }

    cudaMemcpyAsync(d_out, h_, hbytes, cudaMemcpyDeviceToDevice);
}

// round 6
// speedup vs baseline: 1.1794x; 1.1794x over previous
#include <cuda_runtime.h>
#include <cstdint>
#include <cstddef>

// Problem constants (fixed by the reference)
#define NN    50000
#define HH    128
#define TT    4
#define EE    150000
#define G3    384      // 3*H
#define K4    512      // T*H
#define SEGS  (NN*TT)

// ---------------------------------------------------------------------------
// Scratch (no allocations allowed -> __device__ globals)
// ---------------------------------------------------------------------------
__device__ float g_h   [(size_t)NN * HH];
__device__ float g_S   [(size_t)NN * K4];
__device__ float g_inc [(size_t)NN * HH];
__device__ float g_gx  [(size_t)NN * G3];
__device__ float g_gh  [(size_t)NN * G3];
__device__ float g_gx1c[(size_t)NN * G3];
__device__ float g_Wcat[2 * HH * K4];
__device__ int   g_cnt [SEGS];
__device__ int   g_off [SEGS + 1];
__device__ int   g_cur [SEGS];
__device__ int   g_csr [TT * EE];

// ---------------------------------------------------------------------------
// CSR build (edges identical across timesteps -> once per launch)
// ---------------------------------------------------------------------------
__global__ void count_kernel(const int* __restrict__ edges)
{
    int idx = blockIdx.x * blockDim.x + threadIdx.x;
    if (idx >= TT * EE) return;
    int t   = idx / EE;
    int tgt = edges[(size_t)idx * 2 + 1];
    atomicAdd(&g_cnt[tgt * TT + t], 1);
}

__global__ void scan_kernel()
{
    __shared__ int s[1024];
    const int n     = SEGS;
    const int chunk = (n + 1023) / 1024;
    int tid = threadIdx.x;
    int lo  = tid * chunk;
    int hi  = min(lo + chunk, n);

    int sum = 0;
    for (int i = lo; i < hi; ++i) sum += g_cnt[i];
    s[tid] = sum;
    __syncthreads();
    for (int o = 1; o < 1024; o <<= 1) {
        int v = (tid >= o) ? s[tid - o] : 0;
        __syncthreads();
        s[tid] += v;
        __syncthreads();
    }
    int run = (tid == 0) ? 0 : s[tid - 1];
    for (int i = lo; i < hi; ++i) { g_off[i] = run; run += g_cnt[i]; }
    if (tid == 1023) g_off[n] = s[1023];
}

__global__ void fill_kernel(const int* __restrict__ edges)
{
    int idx = blockIdx.x * blockDim.x + threadIdx.x;
    if (idx >= TT * EE) return;
    int t   = idx / EE;
    int src = edges[(size_t)idx * 2 + 0];
    int tgt = edges[(size_t)idx * 2 + 1];
    int seg = tgt * TT + t;
    int pos = atomicAdd(&g_cur[seg], 1);
    g_csr[pos] = src;
}

// Rearrange msg_W (L,T,H,H) -> Wcat[l][f][t*128+k]
__global__ void wcat_kernel(const float* __restrict__ msg_W)
{
    int idx = blockIdx.x * blockDim.x + threadIdx.x;
    if (idx >= 2 * HH * K4) return;
    int l  = idx / (HH * K4);
    int r  = idx % (HH * K4);
    int f  = r / K4;
    int kk = r % K4;
    int t  = kk >> 7;
    int k  = kk & 127;
    g_Wcat[idx] = msg_W[(((size_t)l * TT + t) * HH + f) * HH + k];
}

// ---------------------------------------------------------------------------
// Aggregation: S[n, t*128+f] = sum over incoming type-t edges of h[src][f]
// ---------------------------------------------------------------------------
__global__ void __launch_bounds__(128)
agg_kernel(const float* __restrict__ h)
{
    int n = blockIdx.x;
    int f = threadIdx.x;
    #pragma unroll
    for (int t = 0; t < TT; ++t) {
        int b = g_off[n * TT + t];
        int e = g_off[n * TT + t + 1];
        float a = 0.f;
        for (int i = b; i < e; ++i)
            a += __ldg(&h[(size_t)g_csr[i] * HH + f]);
        g_S[(size_t)n * K4 + t * HH + f] = a;
    }
}

// ---------------------------------------------------------------------------
// tf32 helpers
// ---------------------------------------------------------------------------
__device__ __forceinline__ float to_tf32(float x)
{
    uint32_t u;
    asm("cvt.rna.tf32.f32 %0, %1;" : "=r"(u) : "f"(x));
    return __uint_as_float(u);
}

__device__ __forceinline__ void mma_tf32(float* c, const uint32_t* a, const uint32_t* b)
{
    asm volatile(
        "mma.sync.aligned.m16n8k8.row.col.f32.tf32.tf32.f32 "
        "{%0,%1,%2,%3}, {%4,%5,%6,%7}, {%8,%9}, {%0,%1,%2,%3};"
        : "+f"(c[0]), "+f"(c[1]), "+f"(c[2]), "+f"(c[3])
        : "r"(a[0]), "r"(a[1]), "r"(a[2]), "r"(a[3]),
          "r"(b[0]), "r"(b[1]));
}

// ---------------------------------------------------------------------------
// Double-buffered tf32 GEMM.
//   C[m, col0+n] = epilogue( sum_k A[m*lda+k] * W[(col0+n)*wld+k] )
//   MODE 0: + bias[col0+n] (may be null) + Cin[m*ldc+col0+n] (may be null)
//   MODE 1: + sum_t deg_t[m] * bl[t*128+f]   (inc epilogue, col0 == 0)
// 128x128 tile, BK=16, 2-stage smem pipeline, 256 threads (8 warps, 4x2).
// One __syncthreads per K-iteration; next tile's LDGs issued before the MMAs.
// ---------------------------------------------------------------------------
#define PSTR 20   // padded stride (words) for BK=16

template<int MODE>
__global__ void __launch_bounds__(256)
gemm_tf32(const float* __restrict__ A, int lda,
          const float* __restrict__ W, int wld,
          const float* __restrict__ bias,
          const float* __restrict__ Cin,
          float* __restrict__ C, int ldc,
          int M, int K)
{
    __shared__ float As[2][128 * PSTR];
    __shared__ float Bs[2][128 * PSTR];
    __shared__ float sb[512];

    const int tid  = threadIdx.x;
    const int lane = tid & 31;
    const int warp = tid >> 5;
    const int wm   = warp & 3;
    const int wn   = warp >> 2;
    const int row0 = blockIdx.x * 128;
    const int col0 = blockIdx.y * 128;

    if (MODE == 1)
        for (int i = tid; i < 512; i += 256) sb[i] = bias[i];

    // per-thread load coordinates: 2 float4 each for A and B per tile
    const int ldr0 = tid >> 1;                 // unused placeholder
    (void)ldr0;
    int lr[2], lc[2];
    #pragma unroll
    for (int i = 0; i < 2; ++i) {
        int idx = tid + i * 256;      // 0..511
        lr[i] = idx >> 2;             // 0..127
        lc[i] = (idx & 3) << 2;       // 0,4,8,12
    }

    float acc[2][8][4];
    #pragma unroll
    for (int mi = 0; mi < 2; ++mi)
        #pragma unroll
        for (int ni = 0; ni < 8; ++ni)
            #pragma unroll
            for (int q = 0; q < 4; ++q) acc[mi][ni][q] = 0.f;

    const int gr = lane >> 2;
    const int gc = lane & 3;

    float4 ra[2], rb[2];

    // ---- prologue: load tile 0 ----
    #pragma unroll
    for (int i = 0; i < 2; ++i) {
        ra[i] = make_float4(0.f, 0.f, 0.f, 0.f);
        if (row0 + lr[i] < M)
            ra[i] = *reinterpret_cast<const float4*>(A + (size_t)(row0 + lr[i]) * lda + lc[i]);
        rb[i] = *reinterpret_cast<const float4*>(W + (size_t)(col0 + lr[i]) * wld + lc[i]);
    }
    #pragma unroll
    for (int i = 0; i < 2; ++i) {
        float4 v = ra[i];
        v.x = to_tf32(v.x); v.y = to_tf32(v.y); v.z = to_tf32(v.z); v.w = to_tf32(v.w);
        *reinterpret_cast<float4*>(&As[0][lr[i] * PSTR + lc[i]]) = v;
        float4 w = rb[i];
        w.x = to_tf32(w.x); w.y = to_tf32(w.y); w.z = to_tf32(w.z); w.w = to_tf32(w.w);
        *reinterpret_cast<float4*>(&Bs[0][lr[i] * PSTR + lc[i]]) = w;
    }
    __syncthreads();

    // ---- pipelined mainloop ----
    int buf = 0;
    for (int kt = 0; kt < K; kt += 16) {
        const bool has_next = (kt + 16) < K;
        if (has_next) {
            const int kn = kt + 16;
            #pragma unroll
            for (int i = 0; i < 2; ++i) {
                ra[i] = make_float4(0.f, 0.f, 0.f, 0.f);
                if (row0 + lr[i] < M)
                    ra[i] = *reinterpret_cast<const float4*>(A + (size_t)(row0 + lr[i]) * lda + kn + lc[i]);
                rb[i] = *reinterpret_cast<const float4*>(W + (size_t)(col0 + lr[i]) * wld + kn + lc[i]);
            }
        }

        const float* Ab = As[buf];
        const float* Bb = Bs[buf];
        #pragma unroll
        for (int kq = 0; kq < 2; ++kq) {
            const int kk = kq * 8;
            uint32_t a[2][4];
            #pragma unroll
            for (int mi = 0; mi < 2; ++mi) {
                int am = wm * 32 + mi * 16;
                a[mi][0] = __float_as_uint(Ab[(am + gr)     * PSTR + kk + gc]);
                a[mi][1] = __float_as_uint(Ab[(am + gr + 8) * PSTR + kk + gc]);
                a[mi][2] = __float_as_uint(Ab[(am + gr)     * PSTR + kk + gc + 4]);
                a[mi][3] = __float_as_uint(Ab[(am + gr + 8) * PSTR + kk + gc + 4]);
            }
            #pragma unroll
            for (int ni = 0; ni < 8; ++ni) {
                int bn = wn * 64 + ni * 8;
                uint32_t b[2];
                b[0] = __float_as_uint(Bb[(bn + gr) * PSTR + kk + gc]);
                b[1] = __float_as_uint(Bb[(bn + gr) * PSTR + kk + gc + 4]);
                mma_tf32(acc[0][ni], a[0], b);
                mma_tf32(acc[1][ni], a[1], b);
            }
        }

        if (has_next) {
            const int nb = buf ^ 1;
            #pragma unroll
            for (int i = 0; i < 2; ++i) {
                float4 v = ra[i];
                v.x = to_tf32(v.x); v.y = to_tf32(v.y); v.z = to_tf32(v.z); v.w = to_tf32(v.w);
                *reinterpret_cast<float4*>(&As[nb][lr[i] * PSTR + lc[i]]) = v;
                float4 w = rb[i];
                w.x = to_tf32(w.x); w.y = to_tf32(w.y); w.z = to_tf32(w.z); w.w = to_tf32(w.w);
                *reinterpret_cast<float4*>(&Bs[nb][lr[i] * PSTR + lc[i]]) = w;
            }
            buf = nb;
        }
        __syncthreads();
    }

    // ---- epilogue ----
    #pragma unroll
    for (int mi = 0; mi < 2; ++mi) {
        const int rbase = row0 + wm * 32 + mi * 16 + gr;
        float dg[2][4];
        if (MODE == 1) {
            #pragma unroll
            for (int hh = 0; hh < 2; ++hh) {
                int r = rbase + hh * 8;
                if (r < M) {
                    int o0 = g_off[r*4+0], o1 = g_off[r*4+1], o2 = g_off[r*4+2];
                    int o3 = g_off[r*4+3], o4 = g_off[r*4+4];
                    dg[hh][0] = (float)(o1 - o0); dg[hh][1] = (float)(o2 - o1);
                    dg[hh][2] = (float)(o3 - o2); dg[hh][3] = (float)(o4 - o3);
                }
            }
        }
        #pragma unroll
        for (int ni = 0; ni < 8; ++ni) {
            const int cc = col0 + wn * 64 + ni * 8 + gc * 2;
            #pragma unroll
            for (int hh = 0; hh < 2; ++hh) {
                int r = rbase + hh * 8;
                if (r < M) {
                    float v0 = acc[mi][ni][hh * 2 + 0];
                    float v1 = acc[mi][ni][hh * 2 + 1];
                    if (MODE == 0) {
                        if (bias) { v0 += bias[cc]; v1 += bias[cc + 1]; }
                        if (Cin) {
                            const float* ci = Cin + (size_t)r * ldc + cc;
                            v0 += ci[0]; v1 += ci[1];
                        }
                    } else {
                        int f = cc;   // col0 == 0 for inc
                        v0 += dg[hh][0]*sb[f]     + dg[hh][1]*sb[128+f]
                            + dg[hh][2]*sb[256+f] + dg[hh][3]*sb[384+f];
                        v1 += dg[hh][0]*sb[f+1]     + dg[hh][1]*sb[128+f+1]
                            + dg[hh][2]*sb[256+f+1] + dg[hh][3]*sb[384+f+1];
                    }
                    *reinterpret_cast<float2*>(C + (size_t)r * ldc + cc) = make_float2(v0, v1);
                }
            }
        }
    }
}

// ---------------------------------------------------------------------------
// GRU elementwise update (in place on h)
// ---------------------------------------------------------------------------
__global__ void gru_update_kernel(const float* __restrict__ gx,
                                  const float* __restrict__ gh,
                                  float* __restrict__ h)
{
    int idx = blockIdx.x * blockDim.x + threadIdx.x;
    if (idx >= NN * HH) return;
    int m = idx >> 7;
    int n = idx & 127;

    size_t base = (size_t)m * G3 + n;
    float xr = gx[base +   0], xz = gx[base + 128], xn = gx[base + 256];
    float hr = gh[base +   0], hz = gh[base + 128], hn = gh[base + 256];

    float r = 1.0f / (1.0f + expf(-(xr + hr)));
    float z = 1.0f / (1.0f + expf(-(xz + hz)));
    float nv = tanhf(xn + r * hn);
    float hv = h[idx];
    h[idx] = (1.0f - z) * nv + z * hv;
}

// ---------------------------------------------------------------------------
// Launch
// ---------------------------------------------------------------------------
extern "C" void kernel_launch(void* const* d_in, const int* in_sizes, int n_in,
                              void* d_out, int out_size)
{
    const float* x        = (const float*)d_in[0];
    const int*   edges    = (const int*)  d_in[1];
    const float* msg_W    = (const float*)d_in[2];
    const float* msg_b    = (const float*)d_in[3];
    const float* g0_Wih   = (const float*)d_in[4];
    const float* g0_Whh   = (const float*)d_in[5];
    const float* g0_bih   = (const float*)d_in[6];
    const float* g0_bhh   = (const float*)d_in[7];
    const float* g1_Wih   = (const float*)d_in[8];   // (384, 256)
    const float* g1_Whh   = (const float*)d_in[9];
    const float* g1_bih   = (const float*)d_in[10];
    const float* g1_bhh   = (const float*)d_in[11];

    float *h_, *S_, *inc_, *gx_, *gh_, *gx1c_, *Wcat_;
    int *cnt_, *off_, *cur_;
    cudaGetSymbolAddress((void**)&h_,    g_h);
    cudaGetSymbolAddress((void**)&S_,    g_S);
    cudaGetSymbolAddress((void**)&inc_,  g_inc);
    cudaGetSymbolAddress((void**)&gx_,   g_gx);
    cudaGetSymbolAddress((void**)&gh_,   g_gh);
    cudaGetSymbolAddress((void**)&gx1c_, g_gx1c);
    cudaGetSymbolAddress((void**)&Wcat_, g_Wcat);
    cudaGetSymbolAddress((void**)&cnt_,  g_cnt);
    cudaGetSymbolAddress((void**)&off_,  g_off);
    cudaGetSymbolAddress((void**)&cur_,  g_cur);

    const size_t hbytes = (size_t)NN * HH * sizeof(float);

    cudaMemcpyAsync(h_, x, hbytes, cudaMemcpyDeviceToDevice);

    // --- CSR build ---
    cudaMemsetAsync(cnt_, 0, SEGS * sizeof(int));
    count_kernel<<<(TT*EE + 255)/256, 256>>>(edges);
    scan_kernel<<<1, 1024>>>();
    cudaMemcpyAsync(cur_, off_, SEGS * sizeof(int), cudaMemcpyDeviceToDevice);
    fill_kernel<<<(TT*EE + 255)/256, 256>>>(edges);

    // --- Weight rearrange ---
    wcat_kernel<<<(2*HH*K4 + 255)/256, 256>>>(msg_W);

    const dim3 gate_grid((NN + 127)/128, G3/128);
    const dim3 inc_grid ((NN + 127)/128, 1);
    const int  gru_blocks = (NN * HH + 255) / 256;

    // gx1c = x @ Wih1[:, :128]^T + bih1  (constant across layer-1 steps)
    gemm_tf32<0><<<gate_grid, 256>>>(x, HH, g1_Wih, 2*HH, g1_bih, nullptr,
                                     gx1c_, G3, NN, HH);

    // ---- Layer 0: 3 timesteps ----
    for (int s = 0; s < 3; ++s) {
        agg_kernel<<<NN, HH>>>(h_);
        gemm_tf32<1><<<inc_grid, 256>>>(S_, K4, Wcat_ + 0*HH*K4, K4,
                                        msg_b + (size_t)0*TT*HH, nullptr,
                                        inc_, HH, NN, K4);
        gemm_tf32<0><<<gate_grid, 256>>>(inc_, HH, g0_Wih, HH, g0_bih, nullptr,
                                         gx_, G3, NN, HH);
        gemm_tf32<0><<<gate_grid, 256>>>(h_, HH, g0_Whh, HH, g0_bhh, nullptr,
                                         gh_, G3, NN, HH);
        gru_update_kernel<<<gru_blocks, 256>>>(gx_, gh_, h_);
    }

    // ---- Layer 1: 3 timesteps ----
    for (int s = 0; s < 3; ++s) {
        agg_kernel<<<NN, HH>>>(h_);
        gemm_tf32<1><<<inc_grid, 256>>>(S_, K4, Wcat_ + 1*HH*K4, K4,
                                        msg_b + (size_t)1*TT*HH, nullptr,
                                        inc_, HH, NN, K4);
        gemm_tf32<0><<<gate_grid, 256>>>(inc_, HH, g1_Wih + HH, 2*HH, nullptr, gx1c_,
                                         gx_, G3, NN, HH);
        gemm_tf32<0><<<gate_grid, 256>>>(h_, HH, g1_Whh, HH, g1_bhh, nullptr,
                                         gh_, G3, NN, HH);
        gru_update_kernel<<<gru_blocks, 256>>>(gx_, gh_, h_);
    }

    cudaMemcpyAsync(d_out, h_, hbytes, cudaMemcpyDeviceToDevice);
}

// round 8
// speedup vs baseline: 1.3163x; 1.1161x over previous
#include <cuda_runtime.h>
#include <cstdint>
#include <cstddef>

// Problem constants (fixed by the reference)
#define NN    50000
#define HH    128
#define TT    4
#define EE    150000
#define G3    384      // 3*H
#define K4    512      // T*H
#define SEGS  (NN*TT)

// ---------------------------------------------------------------------------
// Scratch (no allocations allowed -> __device__ globals)
// ---------------------------------------------------------------------------
__device__ float g_h   [(size_t)NN * HH];
__device__ float g_S   [(size_t)NN * K4];
__device__ float g_inc [(size_t)NN * HH];
__device__ float g_gx  [(size_t)NN * G3];
__device__ float g_gh  [(size_t)NN * G3];
__device__ float g_gx1c[(size_t)NN * G3];
__device__ float g_Wcat[2 * HH * K4];
__device__ int   g_cnt [SEGS];
__device__ int   g_off [SEGS + 1];
__device__ int   g_cur [SEGS];
__device__ int   g_csr [TT * EE];

// ---------------------------------------------------------------------------
// CSR build (edges identical across timesteps -> once per launch)
// ---------------------------------------------------------------------------
__global__ void count_kernel(const int* __restrict__ edges)
{
    int idx = blockIdx.x * blockDim.x + threadIdx.x;
    if (idx >= TT * EE) return;
    int t   = idx / EE;
    int tgt = edges[(size_t)idx * 2 + 1];
    atomicAdd(&g_cnt[tgt * TT + t], 1);
}

__global__ void scan_kernel()
{
    __shared__ int s[1024];
    const int n     = SEGS;
    const int chunk = (n + 1023) / 1024;
    int tid = threadIdx.x;
    int lo  = tid * chunk;
    int hi  = min(lo + chunk, n);

    int sum = 0;
    for (int i = lo; i < hi; ++i) sum += g_cnt[i];
    s[tid] = sum;
    __syncthreads();
    for (int o = 1; o < 1024; o <<= 1) {
        int v = (tid >= o) ? s[tid - o] : 0;
        __syncthreads();
        s[tid] += v;
        __syncthreads();
    }
    int run = (tid == 0) ? 0 : s[tid - 1];
    for (int i = lo; i < hi; ++i) { g_off[i] = run; run += g_cnt[i]; }
    if (tid == 1023) g_off[n] = s[1023];
}

__global__ void fill_kernel(const int* __restrict__ edges)
{
    int idx = blockIdx.x * blockDim.x + threadIdx.x;
    if (idx >= TT * EE) return;
    int t   = idx / EE;
    int src = edges[(size_t)idx * 2 + 0];
    int tgt = edges[(size_t)idx * 2 + 1];
    int seg = tgt * TT + t;
    int pos = atomicAdd(&g_cur[seg], 1);
    g_csr[pos] = src;
}

// Rearrange msg_W (L,T,H,H) -> Wcat[l][f][t*128+k]
__global__ void wcat_kernel(const float* __restrict__ msg_W)
{
    int idx = blockIdx.x * blockDim.x + threadIdx.x;
    if (idx >= 2 * HH * K4) return;
    int l  = idx / (HH * K4);
    int r  = idx % (HH * K4);
    int f  = r / K4;
    int kk = r % K4;
    int t  = kk >> 7;
    int k  = kk & 127;
    g_Wcat[idx] = msg_W[(((size_t)l * TT + t) * HH + f) * HH + k];
}

// ---------------------------------------------------------------------------
// Aggregation: S[n, t*128+f] = sum over incoming type-t edges of h[src][f]
// ---------------------------------------------------------------------------
__global__ void __launch_bounds__(128)
agg_kernel(const float* __restrict__ h)
{
    int n = blockIdx.x;
    int f = threadIdx.x;
    #pragma unroll
    for (int t = 0; t < TT; ++t) {
        int b = g_off[n * TT + t];
        int e = g_off[n * TT + t + 1];
        float a = 0.f;
        for (int i = b; i < e; ++i)
            a += __ldg(&h[(size_t)g_csr[i] * HH + f]);
        g_S[(size_t)n * K4 + t * HH + f] = a;
    }
}

// ---------------------------------------------------------------------------
// tf32 helpers
// ---------------------------------------------------------------------------
__device__ __forceinline__ float to_tf32(float x)
{
    uint32_t u;
    asm("cvt.rna.tf32.f32 %0, %1;" : "=r"(u) : "f"(x));
    return __uint_as_float(u);
}

__device__ __forceinline__ void mma_tf32(float* c, const uint32_t* a, const uint32_t* b)
{
    asm volatile(
        "mma.sync.aligned.m16n8k8.row.col.f32.tf32.tf32.f32 "
        "{%0,%1,%2,%3}, {%4,%5,%6,%7}, {%8,%9}, {%0,%1,%2,%3};"
        : "+f"(c[0]), "+f"(c[1]), "+f"(c[2]), "+f"(c[3])
        : "r"(a[0]), "r"(a[1]), "r"(a[2]), "r"(a[3]),
          "r"(b[0]), "r"(b[1]));
}

__device__ __forceinline__ void ldsm_x4(uint32_t* r, uint32_t addr)
{
    asm volatile(
        "ldmatrix.sync.aligned.m8n8.x4.shared.b16 {%0,%1,%2,%3}, [%4];"
        : "=r"(r[0]), "=r"(r[1]), "=r"(r[2]), "=r"(r[3]) : "r"(addr));
}

// ---------------------------------------------------------------------------
// Double-buffered tf32 GEMM with LDSM fragment loads.
//   C[m, col0+n] = epilogue( sum_k A[m*lda+k] * W[(col0+n)*wld+k] )
//   MODE 0: + bias[col0+n] (may be null) + Cin[m*ldc+col0+n] (may be null)
//   MODE 1: + sum_t deg_t[m] * bl[t*128+f]   (inc epilogue, col0 == 0)
// 128x128 tile, BK=16, 2-stage smem pipeline, 256 threads (8 warps, 4x2).
// ---------------------------------------------------------------------------
#define PSTR 20   // padded stride (words) for BK=16; conflict-free for LDSM

template<int MODE>
__global__ void __launch_bounds__(256)
gemm_tf32(const float* __restrict__ A, int lda,
          const float* __restrict__ W, int wld,
          const float* __restrict__ bias,
          const float* __restrict__ Cin,
          float* __restrict__ C, int ldc,
          int M, int K)
{
    __shared__ float As[2][128 * PSTR];
    __shared__ float Bs[2][128 * PSTR];
    __shared__ float sb[512];

    const int tid  = threadIdx.x;
    const int lane = tid & 31;
    const int warp = tid >> 5;
    const int wm   = warp & 3;
    const int wn   = warp >> 2;
    const int row0 = blockIdx.x * 128;
    const int col0 = blockIdx.y * 128;

    if (MODE == 1)
        for (int i = tid; i < 512; i += 256) sb[i] = bias[i];

    // per-thread load coordinates: 2 float4 each for A and B per tile
    int lr[2], lc[2];
    #pragma unroll
    for (int i = 0; i < 2; ++i) {
        int idx = tid + i * 256;      // 0..511
        lr[i] = idx >> 2;             // 0..127
        lc[i] = (idx & 3) << 2;       // 0,4,8,12
    }

    float acc[2][8][4];
    #pragma unroll
    for (int mi = 0; mi < 2; ++mi)
        #pragma unroll
        for (int ni = 0; ni < 8; ++ni)
            #pragma unroll
            for (int q = 0; q < 4; ++q) acc[mi][ni][q] = 0.f;

    const int gr = lane >> 2;
    const int gc = lane & 3;

    // ldmatrix per-thread source addresses (shared-space, bytes)
    const uint32_t as0 = (uint32_t)__cvta_generic_to_shared(&As[0][0]);
    const uint32_t bs0 = (uint32_t)__cvta_generic_to_shared(&Bs[0][0]);
    const uint32_t bufbytes = 128 * PSTR * 4;
    // A x4: matrices = (row-half am/am+8) x (col-half kk/kk+4)
    const int a_row = wm * 32 + (lane & 7) + ((lane >> 3) & 1) * 8;
    const int a_col = (lane >> 4) * 4;
    const uint32_t a_off = (uint32_t)((a_row * PSTR + a_col) * 4);
    // B x4: matrices = (n-half bn/bn+8) x (k-half kk/kk+4)
    const int b_row = wn * 64 + ((lane >> 4) & 1) * 8 + (lane & 7);
    const int b_col = ((lane >> 3) & 1) * 4;
    const uint32_t b_off = (uint32_t)((b_row * PSTR + b_col) * 4);

    float4 ra[2], rb[2];

    // ---- prologue: load tile 0 ----
    #pragma unroll
    for (int i = 0; i < 2; ++i) {
        ra[i] = make_float4(0.f, 0.f, 0.f, 0.f);
        if (row0 + lr[i] < M)
            ra[i] = *reinterpret_cast<const float4*>(A + (size_t)(row0 + lr[i]) * lda + lc[i]);
        rb[i] = *reinterpret_cast<const float4*>(W + (size_t)(col0 + lr[i]) * wld + lc[i]);
    }
    #pragma unroll
    for (int i = 0; i < 2; ++i) {
        float4 v = ra[i];
        v.x = to_tf32(v.x); v.y = to_tf32(v.y); v.z = to_tf32(v.z); v.w = to_tf32(v.w);
        *reinterpret_cast<float4*>(&As[0][lr[i] * PSTR + lc[i]]) = v;
        float4 w = rb[i];
        w.x = to_tf32(w.x); w.y = to_tf32(w.y); w.z = to_tf32(w.z); w.w = to_tf32(w.w);
        *reinterpret_cast<float4*>(&Bs[0][lr[i] * PSTR + lc[i]]) = w;
    }
    __syncthreads();

    // ---- pipelined mainloop ----
    int buf = 0;
    for (int kt = 0; kt < K; kt += 16) {
        const bool has_next = (kt + 16) < K;
        if (has_next) {
            const int kn = kt + 16;
            #pragma unroll
            for (int i = 0; i < 2; ++i) {
                ra[i] = make_float4(0.f, 0.f, 0.f, 0.f);
                if (row0 + lr[i] < M)
                    ra[i] = *reinterpret_cast<const float4*>(A + (size_t)(row0 + lr[i]) * lda + kn + lc[i]);
                rb[i] = *reinterpret_cast<const float4*>(W + (size_t)(col0 + lr[i]) * wld + kn + lc[i]);
            }
        }

        const uint32_t abase = as0 + (uint32_t)buf * bufbytes + a_off;
        const uint32_t bbase = bs0 + (uint32_t)buf * bufbytes + b_off;
        #pragma unroll
        for (int kq = 0; kq < 2; ++kq) {
            const uint32_t koff = (uint32_t)(kq * 8 * 4);   // kk words -> bytes
            uint32_t a0[4], a1[4];
            ldsm_x4(a0, abase + koff);
            ldsm_x4(a1, abase + (uint32_t)(16 * PSTR * 4) + koff);
            #pragma unroll
            for (int p = 0; p < 4; ++p) {
                uint32_t b4[4];
                ldsm_x4(b4, bbase + (uint32_t)(p * 16 * PSTR * 4) + koff);
                mma_tf32(acc[0][2*p],     a0, b4);
                mma_tf32(acc[0][2*p + 1], a0, b4 + 2);
                mma_tf32(acc[1][2*p],     a1, b4);
                mma_tf32(acc[1][2*p + 1], a1, b4 + 2);
            }
        }

        if (has_next) {
            const int nb = buf ^ 1;
            #pragma unroll
            for (int i = 0; i < 2; ++i) {
                float4 v = ra[i];
                v.x = to_tf32(v.x); v.y = to_tf32(v.y); v.z = to_tf32(v.z); v.w = to_tf32(v.w);
                *reinterpret_cast<float4*>(&As[nb][lr[i] * PSTR + lc[i]]) = v;
                float4 w = rb[i];
                w.x = to_tf32(w.x); w.y = to_tf32(w.y); w.z = to_tf32(w.z); w.w = to_tf32(w.w);
                *reinterpret_cast<float4*>(&Bs[nb][lr[i] * PSTR + lc[i]]) = w;
            }
            buf = nb;
        }
        __syncthreads();
    }

    // ---- epilogue ----
    #pragma unroll
    for (int mi = 0; mi < 2; ++mi) {
        const int rbase = row0 + wm * 32 + mi * 16 + gr;
        float dg[2][4];
        if (MODE == 1) {
            #pragma unroll
            for (int hh = 0; hh < 2; ++hh) {
                int r = rbase + hh * 8;
                if (r < M) {
                    int o0 = g_off[r*4+0], o1 = g_off[r*4+1], o2 = g_off[r*4+2];
                    int o3 = g_off[r*4+3], o4 = g_off[r*4+4];
                    dg[hh][0] = (float)(o1 - o0); dg[hh][1] = (float)(o2 - o1);
                    dg[hh][2] = (float)(o3 - o2); dg[hh][3] = (float)(o4 - o3);
                }
            }
        }
        #pragma unroll
        for (int ni = 0; ni < 8; ++ni) {
            const int cc = col0 + wn * 64 + ni * 8 + gc * 2;
            #pragma unroll
            for (int hh = 0; hh < 2; ++hh) {
                int r = rbase + hh * 8;
                if (r < M) {
                    float v0 = acc[mi][ni][hh * 2 + 0];
                    float v1 = acc[mi][ni][hh * 2 + 1];
                    if (MODE == 0) {
                        if (bias) { v0 += bias[cc]; v1 += bias[cc + 1]; }
                        if (Cin) {
                            const float* ci = Cin + (size_t)r * ldc + cc;
                            v0 += ci[0]; v1 += ci[1];
                        }
                    } else {
                        int f = cc;   // col0 == 0 for inc
                        v0 += dg[hh][0]*sb[f]     + dg[hh][1]*sb[128+f]
                            + dg[hh][2]*sb[256+f] + dg[hh][3]*sb[384+f];
                        v1 += dg[hh][0]*sb[f+1]     + dg[hh][1]*sb[128+f+1]
                            + dg[hh][2]*sb[256+f+1] + dg[hh][3]*sb[384+f+1];
                    }
                    *reinterpret_cast<float2*>(C + (size_t)r * ldc + cc) = make_float2(v0, v1);
                }
            }
        }
    }
}

// ---------------------------------------------------------------------------
// GRU elementwise update (in place on h)
// ---------------------------------------------------------------------------
__global__ void gru_update_kernel(const float* __restrict__ gx,
                                  const float* __restrict__ gh,
                                  float* __restrict__ h)
{
    int idx = blockIdx.x * blockDim.x + threadIdx.x;
    if (idx >= NN * HH) return;
    int m = idx >> 7;
    int n = idx & 127;

    size_t base = (size_t)m * G3 + n;
    float xr = gx[base +   0], xz = gx[base + 128], xn = gx[base + 256];
    float hr = gh[base +   0], hz = gh[base + 128], hn = gh[base + 256];

    float r = 1.0f / (1.0f + expf(-(xr + hr)));
    float z = 1.0f / (1.0f + expf(-(xz + hz)));
    float nv = tanhf(xn + r * hn);
    float hv = h[idx];
    h[idx] = (1.0f - z) * nv + z * hv;
}

// ---------------------------------------------------------------------------
// Launch
// ---------------------------------------------------------------------------
extern "C" void kernel_launch(void* const* d_in, const int* in_sizes, int n_in,
                              void* d_out, int out_size)
{
    const float* x        = (const float*)d_in[0];
    const int*   edges    = (const int*)  d_in[1];
    const float* msg_W    = (const float*)d_in[2];
    const float* msg_b    = (const float*)d_in[3];
    const float* g0_Wih   = (const float*)d_in[4];
    const float* g0_Whh   = (const float*)d_in[5];
    const float* g0_bih   = (const float*)d_in[6];
    const float* g0_bhh   = (const float*)d_in[7];
    const float* g1_Wih   = (const float*)d_in[8];   // (384, 256)
    const float* g1_Whh   = (const float*)d_in[9];
    const float* g1_bih   = (const float*)d_in[10];
    const float* g1_bhh   = (const float*)d_in[11];

    float *h_, *S_, *inc_, *gx_, *gh_, *gx1c_, *Wcat_;
    int *cnt_, *off_, *cur_;
    cudaGetSymbolAddress((void**)&h_,    g_h);
    cudaGetSymbolAddress((void**)&S_,    g_S);
    cudaGetSymbolAddress((void**)&inc_,  g_inc);
    cudaGetSymbolAddress((void**)&gx_,   g_gx);
    cudaGetSymbolAddress((void**)&gh_,   g_gh);
    cudaGetSymbolAddress((void**)&gx1c_, g_gx1c);
    cudaGetSymbolAddress((void**)&Wcat_, g_Wcat);
    cudaGetSymbolAddress((void**)&cnt_,  g_cnt);
    cudaGetSymbolAddress((void**)&off_,  g_off);
    cudaGetSymbolAddress((void**)&cur_,  g_cur);

    const size_t hbytes = (size_t)NN * HH * sizeof(float);

    cudaMemcpyAsync(h_, x, hbytes, cudaMemcpyDeviceToDevice);

    // --- CSR build ---
    cudaMemsetAsync(cnt_, 0, SEGS * sizeof(int));
    count_kernel<<<(TT*EE + 255)/256, 256>>>(edges);
    scan_kernel<<<1, 1024>>>();
    cudaMemcpyAsync(cur_, off_, SEGS * sizeof(int), cudaMemcpyDeviceToDevice);
    fill_kernel<<<(TT*EE + 255)/256, 256>>>(edges);

    // --- Weight rearrange ---
    wcat_kernel<<<(2*HH*K4 + 255)/256, 256>>>(msg_W);

    const dim3 gate_grid((NN + 127)/128, G3/128);
    const dim3 inc_grid ((NN + 127)/128, 1);
    const int  gru_blocks = (NN * HH + 255) / 256;

    // gx1c = x @ Wih1[:, :128]^T + bih1  (constant across layer-1 steps)
    gemm_tf32<0><<<gate_grid, 256>>>(x, HH, g1_Wih, 2*HH, g1_bih, nullptr,
                                     gx1c_, G3, NN, HH);

    // ---- Layer 0: 3 timesteps ----
    for (int s = 0; s < 3; ++s) {
        agg_kernel<<<NN, HH>>>(h_);
        gemm_tf32<1><<<inc_grid, 256>>>(S_, K4, Wcat_ + 0*HH*K4, K4,
                                        msg_b + (size_t)0*TT*HH, nullptr,
                                        inc_, HH, NN, K4);
        gemm_tf32<0><<<gate_grid, 256>>>(inc_, HH, g0_Wih, HH, g0_bih, nullptr,
                                         gx_, G3, NN, HH);
        gemm_tf32<0><<<gate_grid, 256>>>(h_, HH, g0_Whh, HH, g0_bhh, nullptr,
                                         gh_, G3, NN, HH);
        gru_update_kernel<<<gru_blocks, 256>>>(gx_, gh_, h_);
    }

    // ---- Layer 1: 3 timesteps ----
    for (int s = 0; s < 3; ++s) {
        agg_kernel<<<NN, HH>>>(h_);
        gemm_tf32<1><<<inc_grid, 256>>>(S_, K4, Wcat_ + 1*HH*K4, K4,
                                        msg_b + (size_t)1*TT*HH, nullptr,
                                        inc_, HH, NN, K4);
        gemm_tf32<0><<<gate_grid, 256>>>(inc_, HH, g1_Wih + HH, 2*HH, nullptr, gx1c_,
                                         gx_, G3, NN, HH);
        gemm_tf32<0><<<gate_grid, 256>>>(h_, HH, g1_Whh, HH, g1_bhh, nullptr,
                                         gh_, G3, NN, HH);
        gru_update_kernel<<<gru_blocks, 256>>>(gx_, gh_, h_);
    }

    cudaMemcpyAsync(d_out, h_, hbytes, cudaMemcpyDeviceToDevice);
}

// round 9
// speedup vs baseline: 1.3247x; 1.0064x over previous
#include <cuda_runtime.h>
#include <cstdint>
#include <cstddef>

// Problem constants (fixed by the reference)
#define NN    50000
#define HH    128
#define TT    4
#define EE    150000
#define K4    512      // T*H
#define SEGS  (NN*TT)

// ---------------------------------------------------------------------------
// Scratch (no allocations allowed -> __device__ globals)
// ---------------------------------------------------------------------------
__device__ float g_h    [(size_t)NN * HH];
__device__ float g_S    [(size_t)NN * K4];
__device__ float g_inc  [(size_t)NN * HH];
__device__ float g_gates[(size_t)NN * 384];  // r|z|xn pre-activations
__device__ float g_gc1  [(size_t)NN * 384];  // layer1 constant x-part (gates layout)
__device__ float g_Wcat [2 * HH * K4];
__device__ float g_Wrz0 [256 * 256];
__device__ float g_Wrz1 [256 * 256];
__device__ float g_b0cat[384];
__device__ float g_brz1 [256];
__device__ int   g_cnt  [SEGS];
__device__ int   g_off  [SEGS + 1];
__device__ int   g_cur  [SEGS];
__device__ int   g_csr  [TT * EE];

// ---------------------------------------------------------------------------
// CSR build (edges identical across timesteps -> once per launch)
// ---------------------------------------------------------------------------
__global__ void count_kernel(const int* __restrict__ edges)
{
    int idx = blockIdx.x * blockDim.x + threadIdx.x;
    if (idx >= TT * EE) return;
    int t   = idx / EE;
    int tgt = edges[(size_t)idx * 2 + 1];
    atomicAdd(&g_cnt[tgt * TT + t], 1);
}

__global__ void scan_kernel()
{
    __shared__ int s[1024];
    const int n     = SEGS;
    const int chunk = (n + 1023) / 1024;
    int tid = threadIdx.x;
    int lo  = tid * chunk;
    int hi  = min(lo + chunk, n);

    int sum = 0;
    for (int i = lo; i < hi; ++i) sum += g_cnt[i];
    s[tid] = sum;
    __syncthreads();
    for (int o = 1; o < 1024; o <<= 1) {
        int v = (tid >= o) ? s[tid - o] : 0;
        __syncthreads();
        s[tid] += v;
        __syncthreads();
    }
    int run = (tid == 0) ? 0 : s[tid - 1];
    for (int i = lo; i < hi; ++i) { g_off[i] = run; run += g_cnt[i]; }
    if (tid == 1023) g_off[n] = s[1023];
}

__global__ void fill_kernel(const int* __restrict__ edges)
{
    int idx = blockIdx.x * blockDim.x + threadIdx.x;
    if (idx >= TT * EE) return;
    int t   = idx / EE;
    int src = edges[(size_t)idx * 2 + 0];
    int tgt = edges[(size_t)idx * 2 + 1];
    int seg = tgt * TT + t;
    int pos = atomicAdd(&g_cur[seg], 1);
    g_csr[pos] = src;
}

// Rearrange msg_W (L,T,H,H) -> Wcat[l][f][t*128+k]
__global__ void wcat_kernel(const float* __restrict__ msg_W)
{
    int idx = blockIdx.x * blockDim.x + threadIdx.x;
    if (idx >= 2 * HH * K4) return;
    int l  = idx / (HH * K4);
    int r  = idx % (HH * K4);
    int f  = r / K4;
    int kk = r % K4;
    int t  = kk >> 7;
    int k  = kk & 127;
    g_Wcat[idx] = msg_W[(((size_t)l * TT + t) * HH + f) * HH + k];
}

// Build Wrz0, Wrz1, b0cat, brz1
__global__ void build_prep(const float* __restrict__ W0i, const float* __restrict__ W0h,
                           const float* __restrict__ b0i, const float* __restrict__ b0h,
                           const float* __restrict__ W1i, const float* __restrict__ W1h,
                           const float* __restrict__ b1i, const float* __restrict__ b1h)
{
    int idx = blockIdx.x * blockDim.x + threadIdx.x;
    if (idx < 65536) {
        int j = idx >> 8, k = idx & 255;
        g_Wrz0[idx] = (k < 128) ? W0i[j * 128 + k] : W0h[j * 128 + (k - 128)];
    } else if (idx < 131072) {
        int r = idx - 65536;
        int j = r >> 8, k = r & 255;
        g_Wrz1[r] = (k < 128) ? W1i[j * 256 + 128 + k] : W1h[j * 128 + (k - 128)];
    } else if (idx < 131072 + 384) {
        int j = idx - 131072;
        g_b0cat[j] = (j < 256) ? (b0i[j] + b0h[j]) : b0i[j];
    } else if (idx < 131072 + 384 + 256) {
        int j = idx - 131072 - 384;
        g_brz1[j] = b1i[j] + b1h[j];
    }
}

// ---------------------------------------------------------------------------
// Aggregation: S[n, t*128+f] = sum over incoming type-t edges of h[src][f]
// ---------------------------------------------------------------------------
__global__ void __launch_bounds__(128)
agg_kernel(const float* __restrict__ h)
{
    int n = blockIdx.x;
    int f = threadIdx.x;
    #pragma unroll
    for (int t = 0; t < TT; ++t) {
        int b = g_off[n * TT + t];
        int e = g_off[n * TT + t + 1];
        float a = 0.f;
        for (int i = b; i < e; ++i)
            a += __ldg(&h[(size_t)g_csr[i] * HH + f]);
        g_S[(size_t)n * K4 + t * HH + f] = a;
    }
}

// ---------------------------------------------------------------------------
// tf32 helpers
// ---------------------------------------------------------------------------
__device__ __forceinline__ float to_tf32(float x)
{
    uint32_t u;
    asm("cvt.rna.tf32.f32 %0, %1;" : "=r"(u) : "f"(x));
    return __uint_as_float(u);
}

__device__ __forceinline__ void mma_tf32(float* c, const uint32_t* a, const uint32_t* b)
{
    asm volatile(
        "mma.sync.aligned.m16n8k8.row.col.f32.tf32.tf32.f32 "
        "{%0,%1,%2,%3}, {%4,%5,%6,%7}, {%8,%9}, {%0,%1,%2,%3};"
        : "+f"(c[0]), "+f"(c[1]), "+f"(c[2]), "+f"(c[3])
        : "r"(a[0]), "r"(a[1]), "r"(a[2]), "r"(a[3]),
          "r"(b[0]), "r"(b[1]));
}

__device__ __forceinline__ void ldsm_x4(uint32_t* r, uint32_t addr)
{
    asm volatile(
        "ldmatrix.sync.aligned.m8n8.x4.shared.b16 {%0,%1,%2,%3}, [%4];"
        : "=r"(r[0]), "=r"(r[1]), "=r"(r[2]), "=r"(r[3]) : "r"(addr));
}

#define PSTR 20   // padded stride (words) for BK=16; conflict-free for LDSM

// shared fragment-address helpers (identical in all GEMM kernels)
struct FragAddr {
    uint32_t a_off, b_off;
    int gr, gc, wm, wn;
};
__device__ __forceinline__ FragAddr frag_addr(int tid)
{
    FragAddr fa;
    const int lane = tid & 31;
    const int warp = tid >> 5;
    fa.wm = warp & 3;
    fa.wn = warp >> 2;
    fa.gr = lane >> 2;
    fa.gc = lane & 3;
    const int a_row = fa.wm * 32 + (lane & 7) + ((lane >> 3) & 1) * 8;
    const int a_col = (lane >> 4) * 4;
    fa.a_off = (uint32_t)((a_row * PSTR + a_col) * 4);
    const int b_row = fa.wn * 64 + ((lane >> 4) & 1) * 8 + (lane & 7);
    const int b_col = ((lane >> 3) & 1) * 4;
    fa.b_off = (uint32_t)((b_row * PSTR + b_col) * 4);
    return fa;
}

// MMA over one staged 16-K tile
__device__ __forceinline__ void mma_tile(float acc[2][8][4], uint32_t abase, uint32_t bbase)
{
    #pragma unroll
    for (int kq = 0; kq < 2; ++kq) {
        const uint32_t koff = (uint32_t)(kq * 8 * 4);
        uint32_t a0[4], a1[4];
        ldsm_x4(a0, abase + koff);
        ldsm_x4(a1, abase + (uint32_t)(16 * PSTR * 4) + koff);
        #pragma unroll
        for (int p = 0; p < 4; ++p) {
            uint32_t b4[4];
            ldsm_x4(b4, bbase + (uint32_t)(p * 16 * PSTR * 4) + koff);
            mma_tf32(acc[0][2*p],     a0, b4);
            mma_tf32(acc[0][2*p + 1], a0, b4 + 2);
            mma_tf32(acc[1][2*p],     a1, b4);
            mma_tf32(acc[1][2*p + 1], a1, b4 + 2);
        }
    }
}

__device__ __forceinline__ void stage_tile(float* dst, const float4& v, int lr, int lc)
{
    float4 t = v;
    t.x = to_tf32(t.x); t.y = to_tf32(t.y); t.z = to_tf32(t.z); t.w = to_tf32(t.w);
    *reinterpret_cast<float4*>(dst + lr * PSTR + lc) = t;
}

// ---------------------------------------------------------------------------
// General GEMM (MODE 0: bias/Cin epilogue; MODE 1: inc degree-bias epilogue)
// ---------------------------------------------------------------------------
template<int MODE>
__global__ void __launch_bounds__(256)
gemm_tf32(const float* __restrict__ A, int lda,
          const float* __restrict__ W, int wld,
          const float* __restrict__ bias,
          const float* __restrict__ Cin,
          float* __restrict__ C, int ldc,
          int M, int K)
{
    __shared__ float As[2][128 * PSTR];
    __shared__ float Bs[2][128 * PSTR];
    __shared__ float sb[512];

    const int tid  = threadIdx.x;
    const int row0 = blockIdx.x * 128;
    const int col0 = blockIdx.y * 128;
    const FragAddr fa = frag_addr(tid);

    if (MODE == 1)
        for (int i = tid; i < 512; i += 256) sb[i] = bias[i];

    int lr[2], lc[2];
    #pragma unroll
    for (int i = 0; i < 2; ++i) {
        int idx = tid + i * 256;
        lr[i] = idx >> 2;
        lc[i] = (idx & 3) << 2;
    }

    float acc[2][8][4];
    #pragma unroll
    for (int mi = 0; mi < 2; ++mi)
        #pragma unroll
        for (int ni = 0; ni < 8; ++ni)
            #pragma unroll
            for (int q = 0; q < 4; ++q) acc[mi][ni][q] = 0.f;

    const uint32_t as0 = (uint32_t)__cvta_generic_to_shared(&As[0][0]);
    const uint32_t bs0 = (uint32_t)__cvta_generic_to_shared(&Bs[0][0]);
    const uint32_t bufbytes = 128 * PSTR * 4;

    float4 ra[2], rb[2];
    #pragma unroll
    for (int i = 0; i < 2; ++i) {
        ra[i] = make_float4(0.f, 0.f, 0.f, 0.f);
        if (row0 + lr[i] < M)
            ra[i] = *reinterpret_cast<const float4*>(A + (size_t)(row0 + lr[i]) * lda + lc[i]);
        rb[i] = *reinterpret_cast<const float4*>(W + (size_t)(col0 + lr[i]) * wld + lc[i]);
    }
    #pragma unroll
    for (int i = 0; i < 2; ++i) {
        stage_tile(As[0], ra[i], lr[i], lc[i]);
        stage_tile(Bs[0], rb[i], lr[i], lc[i]);
    }
    __syncthreads();

    int buf = 0;
    for (int kt = 0; kt < K; kt += 16) {
        const bool has_next = (kt + 16) < K;
        if (has_next) {
            const int kn = kt + 16;
            #pragma unroll
            for (int i = 0; i < 2; ++i) {
                ra[i] = make_float4(0.f, 0.f, 0.f, 0.f);
                if (row0 + lr[i] < M)
                    ra[i] = *reinterpret_cast<const float4*>(A + (size_t)(row0 + lr[i]) * lda + kn + lc[i]);
                rb[i] = *reinterpret_cast<const float4*>(W + (size_t)(col0 + lr[i]) * wld + kn + lc[i]);
            }
        }

        mma_tile(acc, as0 + (uint32_t)buf * bufbytes + fa.a_off,
                      bs0 + (uint32_t)buf * bufbytes + fa.b_off);

        if (has_next) {
            const int nb = buf ^ 1;
            #pragma unroll
            for (int i = 0; i < 2; ++i) {
                stage_tile(As[nb], ra[i], lr[i], lc[i]);
                stage_tile(Bs[nb], rb[i], lr[i], lc[i]);
            }
            buf = nb;
        }
        __syncthreads();
    }

    #pragma unroll
    for (int mi = 0; mi < 2; ++mi) {
        const int rbase = row0 + fa.wm * 32 + mi * 16 + fa.gr;
        float dg[2][4];
        if (MODE == 1) {
            #pragma unroll
            for (int hh = 0; hh < 2; ++hh) {
                int r = rbase + hh * 8;
                if (r < M) {
                    int o0 = g_off[r*4+0], o1 = g_off[r*4+1], o2 = g_off[r*4+2];
                    int o3 = g_off[r*4+3], o4 = g_off[r*4+4];
                    dg[hh][0] = (float)(o1 - o0); dg[hh][1] = (float)(o2 - o1);
                    dg[hh][2] = (float)(o3 - o2); dg[hh][3] = (float)(o4 - o3);
                }
            }
        }
        #pragma unroll
        for (int ni = 0; ni < 8; ++ni) {
            const int cc = col0 + fa.wn * 64 + ni * 8 + fa.gc * 2;
            #pragma unroll
            for (int hh = 0; hh < 2; ++hh) {
                int r = rbase + hh * 8;
                if (r < M) {
                    float v0 = acc[mi][ni][hh * 2 + 0];
                    float v1 = acc[mi][ni][hh * 2 + 1];
                    if (MODE == 0) {
                        if (bias) { v0 += bias[cc]; v1 += bias[cc + 1]; }
                        if (Cin) {
                            const float* ci = Cin + (size_t)r * ldc + cc;
                            v0 += ci[0]; v1 += ci[1];
                        }
                    } else {
                        int f = cc;
                        v0 += dg[hh][0]*sb[f]     + dg[hh][1]*sb[128+f]
                            + dg[hh][2]*sb[256+f] + dg[hh][3]*sb[384+f];
                        v1 += dg[hh][0]*sb[f+1]     + dg[hh][1]*sb[128+f+1]
                            + dg[hh][2]*sb[256+f+1] + dg[hh][3]*sb[384+f+1];
                    }
                    *reinterpret_cast<float2*>(C + (size_t)r * ldc + cc) = make_float2(v0, v1);
                }
            }
        }
    }
}

// ---------------------------------------------------------------------------
// Gates kernel: writes g_gates[N][384] = [r | z | xn] pre-activations.
// grid (391, 3): y=0/1 -> rz halves (A=[inc|h], K=256, W=Wrz rows y*128..)
//                y=2   -> xn        (A=inc,     K=128, W=Wxn)
// bias (layer0) or Cin=gc1 (layer1); exactly one is non-null.
// ---------------------------------------------------------------------------
__global__ void __launch_bounds__(256)
gates_kernel(const float* __restrict__ inc, const float* __restrict__ h,
             const float* __restrict__ Wrz,           // [256][256]
             const float* __restrict__ Wxn, int wxld, // rows stride wxld
             const float* __restrict__ bias,          // b0cat[384] or null
             const float* __restrict__ Cin,           // gc1[N][384] or null
             float* __restrict__ gates)
{
    __shared__ float As[2][128 * PSTR];
    __shared__ float Bs[2][128 * PSTR];

    const int tid   = threadIdx.x;
    const int row0  = blockIdx.x * 128;
    const int y     = blockIdx.y;
    const int ccol0 = y * 128;
    const bool is_rz = (y < 2);
    const int K     = is_rz ? 256 : 128;
    const float* W  = is_rz ? (Wrz + y * 128 * 256) : Wxn;
    const int wld   = is_rz ? 256 : wxld;
    const FragAddr fa = frag_addr(tid);

    int lr[2], lc[2];
    #pragma unroll
    for (int i = 0; i < 2; ++i) {
        int idx = tid + i * 256;
        lr[i] = idx >> 2;
        lc[i] = (idx & 3) << 2;
    }

    float acc[2][8][4];
    #pragma unroll
    for (int mi = 0; mi < 2; ++mi)
        #pragma unroll
        for (int ni = 0; ni < 8; ++ni)
            #pragma unroll
            for (int q = 0; q < 4; ++q) acc[mi][ni][q] = 0.f;

    const uint32_t as0 = (uint32_t)__cvta_generic_to_shared(&As[0][0]);
    const uint32_t bs0 = (uint32_t)__cvta_generic_to_shared(&Bs[0][0]);
    const uint32_t bufbytes = 128 * PSTR * 4;

    float4 ra[2], rb[2];
    // prologue: kt = 0 -> A source is inc
    #pragma unroll
    for (int i = 0; i < 2; ++i) {
        ra[i] = make_float4(0.f, 0.f, 0.f, 0.f);
        if (row0 + lr[i] < NN)
            ra[i] = *reinterpret_cast<const float4*>(inc + (size_t)(row0 + lr[i]) * HH + lc[i]);
        rb[i] = *reinterpret_cast<const float4*>(W + (size_t)lr[i] * wld + lc[i]);
    }
    #pragma unroll
    for (int i = 0; i < 2; ++i) {
        stage_tile(As[0], ra[i], lr[i], lc[i]);
        stage_tile(Bs[0], rb[i], lr[i], lc[i]);
    }
    __syncthreads();

    int buf = 0;
    for (int kt = 0; kt < K; kt += 16) {
        const bool has_next = (kt + 16) < K;
        if (has_next) {
            const int kn = kt + 16;
            const float* Ap = (kn < 128) ? inc : h;
            const int kl = kn & 127;
            #pragma unroll
            for (int i = 0; i < 2; ++i) {
                ra[i] = make_float4(0.f, 0.f, 0.f, 0.f);
                if (row0 + lr[i] < NN)
                    ra[i] = *reinterpret_cast<const float4*>(Ap + (size_t)(row0 + lr[i]) * HH + kl + lc[i]);
                rb[i] = *reinterpret_cast<const float4*>(W + (size_t)lr[i] * wld + kn + lc[i]);
            }
        }

        mma_tile(acc, as0 + (uint32_t)buf * bufbytes + fa.a_off,
                      bs0 + (uint32_t)buf * bufbytes + fa.b_off);

        if (has_next) {
            const int nb = buf ^ 1;
            #pragma unroll
            for (int i = 0; i < 2; ++i) {
                stage_tile(As[nb], ra[i], lr[i], lc[i]);
                stage_tile(Bs[nb], rb[i], lr[i], lc[i]);
            }
            buf = nb;
        }
        __syncthreads();
    }

    #pragma unroll
    for (int mi = 0; mi < 2; ++mi) {
        const int rbase = row0 + fa.wm * 32 + mi * 16 + fa.gr;
        #pragma unroll
        for (int ni = 0; ni < 8; ++ni) {
            const int ncc = fa.wn * 64 + ni * 8 + fa.gc * 2;   // 0..127 local
            const int cc  = ccol0 + ncc;
            #pragma unroll
            for (int hh = 0; hh < 2; ++hh) {
                int r = rbase + hh * 8;
                if (r < NN) {
                    float v0 = acc[mi][ni][hh * 2 + 0];
                    float v1 = acc[mi][ni][hh * 2 + 1];
                    if (bias) { v0 += bias[cc]; v1 += bias[cc + 1]; }
                    if (Cin) {
                        const float* ci = Cin + (size_t)r * 384 + cc;
                        v0 += ci[0]; v1 += ci[1];
                    }
                    *reinterpret_cast<float2*>(gates + (size_t)r * 384 + cc) = make_float2(v0, v1);
                }
            }
        }
    }
}

// ---------------------------------------------------------------------------
// hn GEMM + fused GRU epilogue: h_new = (1-z)*tanh(xn + r*hn) + z*h
// A = h (K=128), W = Whn[128][128]; grid (391, 1). In-place on h.
// ---------------------------------------------------------------------------
__global__ void __launch_bounds__(256)
hn_gru_kernel(const float* __restrict__ hin,
              const float* __restrict__ Whn,   // Whh + 256*128, wld = 128
              const float* __restrict__ bhn,   // bhh + 256
              const float* __restrict__ gates,
              float* __restrict__ hout)
{
    __shared__ float As[2][128 * PSTR];
    __shared__ float Bs[2][128 * PSTR];

    const int tid  = threadIdx.x;
    const int row0 = blockIdx.x * 128;
    const FragAddr fa = frag_addr(tid);

    int lr[2], lc[2];
    #pragma unroll
    for (int i = 0; i < 2; ++i) {
        int idx = tid + i * 256;
        lr[i] = idx >> 2;
        lc[i] = (idx & 3) << 2;
    }

    float acc[2][8][4];
    #pragma unroll
    for (int mi = 0; mi < 2; ++mi)
        #pragma unroll
        for (int ni = 0; ni < 8; ++ni)
            #pragma unroll
            for (int q = 0; q < 4; ++q) acc[mi][ni][q] = 0.f;

    const uint32_t as0 = (uint32_t)__cvta_generic_to_shared(&As[0][0]);
    const uint32_t bs0 = (uint32_t)__cvta_generic_to_shared(&Bs[0][0]);
    const uint32_t bufbytes = 128 * PSTR * 4;

    float4 ra[2], rb[2];
    #pragma unroll
    for (int i = 0; i < 2; ++i) {
        ra[i] = make_float4(0.f, 0.f, 0.f, 0.f);
        if (row0 + lr[i] < NN)
            ra[i] = *reinterpret_cast<const float4*>(hin + (size_t)(row0 + lr[i]) * HH + lc[i]);
        rb[i] = *reinterpret_cast<const float4*>(Whn + (size_t)lr[i] * HH + lc[i]);
    }
    #pragma unroll
    for (int i = 0; i < 2; ++i) {
        stage_tile(As[0], ra[i], lr[i], lc[i]);
        stage_tile(Bs[0], rb[i], lr[i], lc[i]);
    }
    __syncthreads();

    int buf = 0;
    for (int kt = 0; kt < 128; kt += 16) {
        const bool has_next = (kt + 16) < 128;
        if (has_next) {
            const int kn = kt + 16;
            #pragma unroll
            for (int i = 0; i < 2; ++i) {
                ra[i] = make_float4(0.f, 0.f, 0.f, 0.f);
                if (row0 + lr[i] < NN)
                    ra[i] = *reinterpret_cast<const float4*>(hin + (size_t)(row0 + lr[i]) * HH + kn + lc[i]);
                rb[i] = *reinterpret_cast<const float4*>(Whn + (size_t)lr[i] * HH + kn + lc[i]);
            }
        }

        mma_tile(acc, as0 + (uint32_t)buf * bufbytes + fa.a_off,
                      bs0 + (uint32_t)buf * bufbytes + fa.b_off);

        if (has_next) {
            const int nb = buf ^ 1;
            #pragma unroll
            for (int i = 0; i < 2; ++i) {
                stage_tile(As[nb], ra[i], lr[i], lc[i]);
                stage_tile(Bs[nb], rb[i], lr[i], lc[i]);
            }
            buf = nb;
        }
        __syncthreads();
    }

    // ---- GRU epilogue ----
    #pragma unroll
    for (int mi = 0; mi < 2; ++mi) {
        const int rbase = row0 + fa.wm * 32 + mi * 16 + fa.gr;
        #pragma unroll
        for (int ni = 0; ni < 8; ++ni) {
            const int cc = fa.wn * 64 + ni * 8 + fa.gc * 2;
            #pragma unroll
            for (int hh = 0; hh < 2; ++hh) {
                int r = rbase + hh * 8;
                if (r < NN) {
                    float hn0 = acc[mi][ni][hh * 2 + 0] + bhn[cc];
                    float hn1 = acc[mi][ni][hh * 2 + 1] + bhn[cc + 1];
                    const float* g = gates + (size_t)r * 384;
                    float2 rv = *reinterpret_cast<const float2*>(g + cc);
                    float2 zv = *reinterpret_cast<const float2*>(g + 128 + cc);
                    float2 xn = *reinterpret_cast<const float2*>(g + 256 + cc);
                    float2 hv = *reinterpret_cast<const float2*>(hin + (size_t)r * HH + cc);
                    float r0 = 1.0f / (1.0f + expf(-rv.x));
                    float r1 = 1.0f / (1.0f + expf(-rv.y));
                    float z0 = 1.0f / (1.0f + expf(-zv.x));
                    float z1 = 1.0f / (1.0f + expf(-zv.y));
                    float n0 = tanhf(xn.x + r0 * hn0);
                    float n1 = tanhf(xn.y + r1 * hn1);
                    float o0 = (1.0f - z0) * n0 + z0 * hv.x;
                    float o1 = (1.0f - z1) * n1 + z1 * hv.y;
                    *reinterpret_cast<float2*>(hout + (size_t)r * HH + cc) = make_float2(o0, o1);
                }
            }
        }
    }
}

// ---------------------------------------------------------------------------
// Launch
// ---------------------------------------------------------------------------
extern "C" void kernel_launch(void* const* d_in, const int* in_sizes, int n_in,
                              void* d_out, int out_size)
{
    const float* x        = (const float*)d_in[0];
    const int*   edges    = (const int*)  d_in[1];
    const float* msg_W    = (const float*)d_in[2];
    const float* msg_b    = (const float*)d_in[3];
    const float* g0_Wih   = (const float*)d_in[4];
    const float* g0_Whh   = (const float*)d_in[5];
    const float* g0_bih   = (const float*)d_in[6];
    const float* g0_bhh   = (const float*)d_in[7];
    const float* g1_Wih   = (const float*)d_in[8];   // (384, 256)
    const float* g1_Whh   = (const float*)d_in[9];
    const float* g1_bih   = (const float*)d_in[10];
    const float* g1_bhh   = (const float*)d_in[11];

    float *h_, *S_, *inc_, *gates_, *gc1_, *Wcat_, *Wrz0_, *Wrz1_, *b0cat_, *brz1_;
    int *cnt_, *off_, *cur_;
    cudaGetSymbolAddress((void**)&h_,     g_h);
    cudaGetSymbolAddress((void**)&S_,     g_S);
    cudaGetSymbolAddress((void**)&inc_,   g_inc);
    cudaGetSymbolAddress((void**)&gates_, g_gates);
    cudaGetSymbolAddress((void**)&gc1_,   g_gc1);
    cudaGetSymbolAddress((void**)&Wcat_,  g_Wcat);
    cudaGetSymbolAddress((void**)&Wrz0_,  g_Wrz0);
    cudaGetSymbolAddress((void**)&Wrz1_,  g_Wrz1);
    cudaGetSymbolAddress((void**)&b0cat_, g_b0cat);
    cudaGetSymbolAddress((void**)&brz1_,  g_brz1);
    cudaGetSymbolAddress((void**)&cnt_,   g_cnt);
    cudaGetSymbolAddress((void**)&off_,   g_off);
    cudaGetSymbolAddress((void**)&cur_,   g_cur);

    const size_t hbytes = (size_t)NN * HH * sizeof(float);

    cudaMemcpyAsync(h_, x, hbytes, cudaMemcpyDeviceToDevice);

    // --- CSR build ---
    cudaMemsetAsync(cnt_, 0, SEGS * sizeof(int));
    count_kernel<<<(TT*EE + 255)/256, 256>>>(edges);
    scan_kernel<<<1, 1024>>>();
    cudaMemcpyAsync(cur_, off_, SEGS * sizeof(int), cudaMemcpyDeviceToDevice);
    fill_kernel<<<(TT*EE + 255)/256, 256>>>(edges);

    // --- Weight prep ---
    wcat_kernel<<<(2*HH*K4 + 255)/256, 256>>>(msg_W);
    build_prep<<<(131072 + 640 + 255)/256, 256>>>(g0_Wih, g0_Whh, g0_bih, g0_bhh,
                                                  g1_Wih, g1_Whh, g1_bih, g1_bhh);

    const int  nblk = (NN + 127)/128;   // 391
    const dim3 inc_grid(nblk, 1);
    const dim3 rz1c_grid(nblk, 2);
    const dim3 xn1c_grid(nblk, 1);
    const dim3 gates_grid(nblk, 3);

    // gc1 = x-part of layer1 gates (constant across layer-1 steps)
    // rz half: cols 0..255 of gc1, W = Wih1 rows 0..255 (x-cols 0..127), bias = bih1+bhh1
    gemm_tf32<0><<<rz1c_grid, 256>>>(x, HH, g1_Wih, 2*HH, brz1_, nullptr,
                                     gc1_, 384, NN, HH);
    // xn part: cols 256..383, W = Wih1 rows 256.., bias = bih1[256:]
    gemm_tf32<0><<<xn1c_grid, 256>>>(x, HH, g1_Wih + (size_t)256*256, 2*HH,
                                     g1_bih + 256, nullptr,
                                     gc1_ + 256, 384, NN, HH);

    // ---- Layer 0: 3 timesteps ----
    for (int s = 0; s < 3; ++s) {
        agg_kernel<<<NN, HH>>>(h_);
        gemm_tf32<1><<<inc_grid, 256>>>(S_, K4, Wcat_ + 0*HH*K4, K4,
                                        msg_b + (size_t)0*TT*HH, nullptr,
                                        inc_, HH, NN, K4);
        gates_kernel<<<gates_grid, 256>>>(inc_, h_, Wrz0_,
                                          g0_Wih + (size_t)256*128, 128,
                                          b0cat_, nullptr, gates_);
        hn_gru_kernel<<<nblk, 256>>>(h_, g0_Whh + (size_t)256*128, g0_bhh + 256,
                                     gates_, h_);
    }

    // ---- Layer 1: 3 timesteps ----
    for (int s = 0; s < 3; ++s) {
        agg_kernel<<<NN, HH>>>(h_);
        gemm_tf32<1><<<inc_grid, 256>>>(S_, K4, Wcat_ + 1*HH*K4, K4,
                                        msg_b + (size_t)1*TT*HH, nullptr,
                                        inc_, HH, NN, K4);
        gates_kernel<<<gates_grid, 256>>>(inc_, h_, Wrz1_,
                                          g1_Wih + (size_t)256*256 + 128, 256,
                                          nullptr, gc1_, gates_);
        hn_gru_kernel<<<nblk, 256>>>(h_, g1_Whh + (size_t)256*128, g1_bhh + 256,
                                     gates_, h_);
    }

    cudaMemcpyAsync(d_out, h_, hbytes, cudaMemcpyDeviceToDevice);
}

// round 10
// speedup vs baseline: 1.4644x; 1.1054x over previous
#include <cuda_runtime.h>
#include <cstdint>
#include <cstddef>

// Problem constants (fixed by the reference)
#define NN    50000
#define HH    128
#define TT    4
#define EE    150000
#define K4    512      // T*H
#define SEGS  (NN*TT)

// ---------------------------------------------------------------------------
// Scratch (no allocations allowed -> __device__ globals)
// ---------------------------------------------------------------------------
__device__ __align__(16) float g_h    [(size_t)NN * HH];   // full-precision hidden
__device__ __align__(16) float g_h32  [(size_t)NN * HH];   // tf32-rounded copy of h
__device__ __align__(16) float g_S    [(size_t)NN * K4];   // rounded typed sums
__device__ __align__(16) float g_inc  [(size_t)NN * HH];   // rounded messages
__device__ __align__(16) float g_gates[(size_t)NN * 384];  // r|z|xn pre-activations
__device__ __align__(16) float g_gc1  [(size_t)NN * 384];  // layer1 const x-part
__device__ __align__(16) float g_Wcat [2 * HH * K4];       // rounded
__device__ __align__(16) float g_Wrz0 [256 * 256];         // rounded
__device__ __align__(16) float g_Wrz1 [256 * 256];         // rounded
__device__ __align__(16) float g_W1x  [384 * 128];         // rounded
__device__ __align__(16) float g_Wxn0 [128 * 128];         // rounded
__device__ __align__(16) float g_Wxn1 [128 * 128];         // rounded
__device__ __align__(16) float g_Whn0 [128 * 128];         // rounded
__device__ __align__(16) float g_Whn1 [128 * 128];         // rounded
__device__ float g_b0cat[384];
__device__ float g_b1cat[384];
__device__ int   g_cnt  [SEGS];
__device__ int   g_off  [SEGS + 1];
__device__ int   g_cur  [SEGS];
__device__ int   g_csr  [TT * EE];

// ---------------------------------------------------------------------------
// tf32 helpers
// ---------------------------------------------------------------------------
__device__ __forceinline__ float to_tf32(float x)
{
    uint32_t u;
    asm("cvt.rna.tf32.f32 %0, %1;" : "=r"(u) : "f"(x));
    return __uint_as_float(u);
}

__device__ __forceinline__ void mma_tf32(float* c, const uint32_t* a, const uint32_t* b)
{
    asm volatile(
        "mma.sync.aligned.m16n8k8.row.col.f32.tf32.tf32.f32 "
        "{%0,%1,%2,%3}, {%4,%5,%6,%7}, {%8,%9}, {%0,%1,%2,%3};"
        : "+f"(c[0]), "+f"(c[1]), "+f"(c[2]), "+f"(c[3])
        : "r"(a[0]), "r"(a[1]), "r"(a[2]), "r"(a[3]),
          "r"(b[0]), "r"(b[1]));
}

__device__ __forceinline__ void ldsm_x4(uint32_t* r, uint32_t addr)
{
    asm volatile(
        "ldmatrix.sync.aligned.m8n8.x4.shared.b16 {%0,%1,%2,%3}, [%4];"
        : "=r"(r[0]), "=r"(r[1]), "=r"(r[2]), "=r"(r[3]) : "r"(addr));
}

#define CP_COMMIT() asm volatile("cp.async.commit_group;\n" ::: "memory")
#define CP_WAIT0()  asm volatile("cp.async.wait_group 0;\n" ::: "memory")
#define CP_WAIT1()  asm volatile("cp.async.wait_group 1;\n" ::: "memory")

// ---------------------------------------------------------------------------
// CSR build (edges identical across timesteps -> once per launch)
// ---------------------------------------------------------------------------
__global__ void count_kernel(const int* __restrict__ edges)
{
    int idx = blockIdx.x * blockDim.x + threadIdx.x;
    if (idx >= TT * EE) return;
    int t   = idx / EE;
    int tgt = edges[(size_t)idx * 2 + 1];
    atomicAdd(&g_cnt[tgt * TT + t], 1);
}

__global__ void scan_kernel()
{
    __shared__ int s[1024];
    const int n     = SEGS;
    const int chunk = (n + 1023) / 1024;
    int tid = threadIdx.x;
    int lo  = tid * chunk;
    int hi  = min(lo + chunk, n);

    int sum = 0;
    for (int i = lo; i < hi; ++i) sum += g_cnt[i];
    s[tid] = sum;
    __syncthreads();
    for (int o = 1; o < 1024; o <<= 1) {
        int v = (tid >= o) ? s[tid - o] : 0;
        __syncthreads();
        s[tid] += v;
        __syncthreads();
    }
    int run = (tid == 0) ? 0 : s[tid - 1];
    for (int i = lo; i < hi; ++i) { g_off[i] = run; run += g_cnt[i]; }
    if (tid == 1023) g_off[n] = s[1023];
}

__global__ void fill_kernel(const int* __restrict__ edges)
{
    int idx = blockIdx.x * blockDim.x + threadIdx.x;
    if (idx >= TT * EE) return;
    int t   = idx / EE;
    int src = edges[(size_t)idx * 2 + 0];
    int tgt = edges[(size_t)idx * 2 + 1];
    int seg = tgt * TT + t;
    int pos = atomicAdd(&g_cur[seg], 1);
    g_csr[pos] = src;
}

// Rearrange + round msg_W (L,T,H,H) -> Wcat[l][f][t*128+k]
__global__ void wcat_kernel(const float* __restrict__ msg_W)
{
    int idx = blockIdx.x * blockDim.x + threadIdx.x;
    if (idx >= 2 * HH * K4) return;
    int l  = idx / (HH * K4);
    int r  = idx % (HH * K4);
    int f  = r / K4;
    int kk = r % K4;
    int t  = kk >> 7;
    int k  = kk & 127;
    g_Wcat[idx] = to_tf32(msg_W[(((size_t)l * TT + t) * HH + f) * HH + k]);
}

// Build all rounded gate weights + biases
__global__ void build_prep(const float* __restrict__ W0i, const float* __restrict__ W0h,
                           const float* __restrict__ b0i, const float* __restrict__ b0h,
                           const float* __restrict__ W1i, const float* __restrict__ W1h,
                           const float* __restrict__ b1i, const float* __restrict__ b1h)
{
    int idx = blockIdx.x * blockDim.x + threadIdx.x;
    if (idx < 65536) {
        int j = idx >> 8, k = idx & 255;
        float v = (k < 128) ? W0i[j * 128 + k] : W0h[j * 128 + (k - 128)];
        g_Wrz0[idx] = to_tf32(v);
    } else if (idx < 131072) {
        int r = idx - 65536;
        int j = r >> 8, k = r & 255;
        float v = (k < 128) ? W1i[j * 256 + 128 + k] : W1h[j * 128 + (k - 128)];
        g_Wrz1[r] = to_tf32(v);
    } else if (idx < 180224) {                   // W1x [384][128]
        int r = idx - 131072;
        int j = r >> 7, k = r & 127;
        g_W1x[r] = to_tf32(W1i[j * 256 + k]);
    } else if (idx < 196608) {                   // Wxn0 [128][128]
        int r = idx - 180224;
        int j = r >> 7, k = r & 127;
        g_Wxn0[r] = to_tf32(W0i[(256 + j) * 128 + k]);
    } else if (idx < 212992) {                   // Wxn1
        int r = idx - 196608;
        int j = r >> 7, k = r & 127;
        g_Wxn1[r] = to_tf32(W1i[(256 + j) * 256 + 128 + k]);
    } else if (idx < 229376) {                   // Whn0
        int r = idx - 212992;
        int j = r >> 7, k = r & 127;
        g_Whn0[r] = to_tf32(W0h[(256 + j) * 128 + k]);
    } else if (idx < 245760) {                   // Whn1
        int r = idx - 229376;
        int j = r >> 7, k = r & 127;
        g_Whn1[r] = to_tf32(W1h[(256 + j) * 128 + k]);
    } else if (idx < 246144) {                   // b0cat
        int j = idx - 245760;
        g_b0cat[j] = (j < 256) ? (b0i[j] + b0h[j]) : b0i[j];
    } else if (idx < 246528) {                   // b1cat
        int j = idx - 246144;
        g_b1cat[j] = (j < 256) ? (b1i[j] + b1h[j]) : b1i[j];
    }
}

// h32 = tf32(x)
__global__ void round_kernel(const float* __restrict__ x, float* __restrict__ y)
{
    int idx = blockIdx.x * blockDim.x + threadIdx.x;
    if (idx < NN * HH) y[idx] = to_tf32(x[idx]);
}

// ---------------------------------------------------------------------------
// Aggregation: S[n, t*128+f] = tf32( sum over incoming type-t edges h[src][f] )
// ---------------------------------------------------------------------------
__global__ void __launch_bounds__(128)
agg_kernel(const float* __restrict__ h)
{
    int n = blockIdx.x;
    int f = threadIdx.x;
    #pragma unroll
    for (int t = 0; t < TT; ++t) {
        int b = g_off[n * TT + t];
        int e = g_off[n * TT + t + 1];
        float a = 0.f;
        for (int i = b; i < e; ++i)
            a += __ldg(&h[(size_t)g_csr[i] * HH + f]);
        g_S[(size_t)n * K4 + t * HH + f] = to_tf32(a);
    }
}

// ---------------------------------------------------------------------------
// Pipelined GEMM engine: 128x128 tile, BK=16, 3 stages, cp.async, swizzled smem
// ---------------------------------------------------------------------------
__device__ __forceinline__ uint32_t swoff(int r, int g)   // byte offset in stage
{
    return (uint32_t)((r * 16 + 4 * (g ^ ((r >> 1) & 3))) * 4);
}

struct Frag {
    uint32_t aoff[2][2];   // [mi][kq]
    uint32_t boff[4][2];   // [p][kq]
    int wm, wn, gr, gc;
};

__device__ __forceinline__ Frag make_frag(int tid)
{
    Frag f;
    int lane = tid & 31, warp = tid >> 5;
    f.wm = warp & 3;  f.wn = warp >> 2;
    f.gr = lane >> 2; f.gc = lane & 3;
    int arl = (lane & 7) + ((lane >> 3) & 1) * 8;
    int ga  = lane >> 4;
    int brl = ((lane >> 4) & 1) * 8 + (lane & 7);
    int gb  = (lane >> 3) & 1;
    #pragma unroll
    for (int mi = 0; mi < 2; ++mi)
        #pragma unroll
        for (int kq = 0; kq < 2; ++kq)
            f.aoff[mi][kq] = swoff(f.wm * 32 + mi * 16 + arl, ga + 2 * kq);
    #pragma unroll
    for (int p = 0; p < 4; ++p)
        #pragma unroll
        for (int kq = 0; kq < 2; ++kq)
            f.boff[p][kq] = swoff(f.wn * 64 + p * 16 + brl, gb + 2 * kq);
    return f;
}

__device__ __forceinline__ void mma_stage(float acc[2][8][4],
                                          uint32_t aS, uint32_t bS, const Frag& fg)
{
    #pragma unroll
    for (int kq = 0; kq < 2; ++kq) {
        uint32_t a0[4], a1[4];
        ldsm_x4(a0, aS + fg.aoff[0][kq]);
        ldsm_x4(a1, aS + fg.aoff[1][kq]);
        #pragma unroll
        for (int p = 0; p < 4; ++p) {
            uint32_t b4[4];
            ldsm_x4(b4, bS + fg.boff[p][kq]);
            mma_tf32(acc[0][2*p],     a0, b4);
            mma_tf32(acc[0][2*p + 1], a0, b4 + 2);
            mma_tf32(acc[1][2*p],     a1, b4);
            mma_tf32(acc[1][2*p + 1], a1, b4 + 2);
        }
    }
}

// Issue one 16-K tile (A: 128 rows, guarded; B: 128 weight rows) via cp.async
__device__ __forceinline__ void pipe_issue(uint32_t aS, uint32_t bS,
                                           const float* A0, const float* A1, int lda0,
                                           const float* W, int wld,
                                           int row0, int kt, int tid)
{
    const bool   a1   = (A1 != nullptr) && (kt >= 128);
    const float* Ap   = a1 ? A1 : A0;
    const int    lda  = a1 ? 128 : lda0;
    const int    kc   = a1 ? (kt - 128) : kt;
    #pragma unroll
    for (int i = 0; i < 2; ++i) {
        int slot = tid + i * 256;
        int r = slot >> 2, g = slot & 3;
        uint32_t so = swoff(r, g);
        int rowA = row0 + r;
        int sz = (rowA < NN) ? 16 : 0;
        if (rowA >= NN) rowA = NN - 1;
        const float* sa = Ap + (size_t)rowA * lda + kc + g * 4;
        asm volatile("cp.async.cg.shared.global [%0], [%1], 16, %2;\n"
                     :: "r"(aS + so), "l"(sa), "r"(sz) : "memory");
        const float* sw = W + (size_t)r * wld + kt + g * 4;
        asm volatile("cp.async.cg.shared.global [%0], [%1], 16;\n"
                     :: "r"(bS + so), "l"(sw) : "memory");
    }
}

// Full pipelined mainloop. Stage size = 2048 floats (8192 bytes).
__device__ __forceinline__ void pipe_core(float acc[2][8][4],
                                          uint32_t aB, uint32_t bB,
                                          const float* A0, const float* A1, int lda0,
                                          int K, const float* W, int wld,
                                          int row0, const Frag& fg, int tid)
{
    #pragma unroll
    for (int mi = 0; mi < 2; ++mi)
        #pragma unroll
        for (int ni = 0; ni < 8; ++ni)
            #pragma unroll
            for (int q = 0; q < 4; ++q) acc[mi][ni][q] = 0.f;

    const int niter = K >> 4;
    pipe_issue(aB,        bB,        A0, A1, lda0, W, wld, row0, 0,  tid);
    CP_COMMIT();
    pipe_issue(aB + 8192, bB + 8192, A0, A1, lda0, W, wld, row0, 16, tid);
    CP_COMMIT();

    int st_c = 0;    // compute stage
    for (int i = 0; i < niter; ++i) {
        if (i == niter - 1) { CP_WAIT0(); } else { CP_WAIT1(); }
        __syncthreads();
        if (i + 2 < niter) {
            int st_w = (i + 2) % 3;
            pipe_issue(aB + st_w * 8192, bB + st_w * 8192,
                       A0, A1, lda0, W, wld, row0, (i + 2) * 16, tid);
            CP_COMMIT();
        }
        mma_stage(acc, aB + st_c * 8192, bB + st_c * 8192, fg);
        st_c = (st_c + 1 == 3) ? 0 : st_c + 1;
    }
}

#define PIPE_SMEM \
    __shared__ __align__(16) float As[3 * 2048]; \
    __shared__ __align__(16) float Bs[3 * 2048]; \
    const uint32_t aB = (uint32_t)__cvta_generic_to_shared(As); \
    const uint32_t bB = (uint32_t)__cvta_generic_to_shared(Bs);

// ---------------------------------------------------------------------------
// k_inc: inc[m,f] = tf32( S@Wcat + deg-bias )  (K=512)
// ---------------------------------------------------------------------------
__global__ void __launch_bounds__(256)
k_inc(const float* __restrict__ S, const float* __restrict__ Wc,
      const float* __restrict__ bl, float* __restrict__ inc)
{
    PIPE_SMEM
    const int tid  = threadIdx.x;
    const int row0 = blockIdx.x * 128;
    const Frag fg  = make_frag(tid);

    float acc[2][8][4];
    pipe_core(acc, aB, bB, S, nullptr, K4, K4, Wc, K4, row0, fg, tid);

    #pragma unroll
    for (int mi = 0; mi < 2; ++mi) {
        const int rbase = row0 + fg.wm * 32 + mi * 16 + fg.gr;
        float dg[2][4];
        #pragma unroll
        for (int hh = 0; hh < 2; ++hh) {
            int r = rbase + hh * 8;
            if (r < NN) {
                int o0 = g_off[r*4+0], o1 = g_off[r*4+1], o2 = g_off[r*4+2];
                int o3 = g_off[r*4+3], o4 = g_off[r*4+4];
                dg[hh][0] = (float)(o1 - o0); dg[hh][1] = (float)(o2 - o1);
                dg[hh][2] = (float)(o3 - o2); dg[hh][3] = (float)(o4 - o3);
            }
        }
        #pragma unroll
        for (int ni = 0; ni < 8; ++ni) {
            const int f = fg.wn * 64 + ni * 8 + fg.gc * 2;
            #pragma unroll
            for (int hh = 0; hh < 2; ++hh) {
                int r = rbase + hh * 8;
                if (r < NN) {
                    float v0 = acc[mi][ni][hh * 2 + 0];
                    float v1 = acc[mi][ni][hh * 2 + 1];
                    #pragma unroll
                    for (int t = 0; t < 4; ++t) {
                        float2 bb = *reinterpret_cast<const float2*>(bl + t * 128 + f);
                        v0 += dg[hh][t] * bb.x;
                        v1 += dg[hh][t] * bb.y;
                    }
                    *reinterpret_cast<float2*>(inc + (size_t)r * HH + f) =
                        make_float2(to_tf32(v0), to_tf32(v1));
                }
            }
        }
    }
}

// ---------------------------------------------------------------------------
// k_gates: gates[N][384] = [r | z | xn] pre-activations
// grid (391,3): y<2 -> rz half y (A=[inc|h32], K=256); y=2 -> xn (A=inc, K=128)
// ---------------------------------------------------------------------------
__global__ void __launch_bounds__(256)
k_gates(const float* __restrict__ inc, const float* __restrict__ h32,
        const float* __restrict__ Wrz, const float* __restrict__ Wxn,
        const float* __restrict__ bias,      // b0cat or null
        const float* __restrict__ Cin,       // gc1 or null
        float* __restrict__ gates)
{
    PIPE_SMEM
    const int tid  = threadIdx.x;
    const int row0 = blockIdx.x * 128;
    const int y    = blockIdx.y;
    const Frag fg  = make_frag(tid);

    float acc[2][8][4];
    if (y < 2)
        pipe_core(acc, aB, bB, inc, h32, HH, 256, Wrz + (size_t)y * 128 * 256, 256, row0, fg, tid);
    else
        pipe_core(acc, aB, bB, inc, nullptr, HH, 128, Wxn, 128, row0, fg, tid);

    const int ccol0 = y * 128;
    #pragma unroll
    for (int mi = 0; mi < 2; ++mi) {
        const int rbase = row0 + fg.wm * 32 + mi * 16 + fg.gr;
        #pragma unroll
        for (int ni = 0; ni < 8; ++ni) {
            const int cc = ccol0 + fg.wn * 64 + ni * 8 + fg.gc * 2;
            #pragma unroll
            for (int hh = 0; hh < 2; ++hh) {
                int r = rbase + hh * 8;
                if (r < NN) {
                    float v0 = acc[mi][ni][hh * 2 + 0];
                    float v1 = acc[mi][ni][hh * 2 + 1];
                    if (bias) { v0 += bias[cc]; v1 += bias[cc + 1]; }
                    if (Cin) {
                        float2 ci = *reinterpret_cast<const float2*>(Cin + (size_t)r * 384 + cc);
                        v0 += ci.x; v1 += ci.y;
                    }
                    *reinterpret_cast<float2*>(gates + (size_t)r * 384 + cc) = make_float2(v0, v1);
                }
            }
        }
    }
}

// ---------------------------------------------------------------------------
// k_pre: gc1[N][384] = x-part of layer1 gates (A=h32(x), W=W1x rows y*128, bias b1cat)
// ---------------------------------------------------------------------------
__global__ void __launch_bounds__(256)
k_pre(const float* __restrict__ h32, const float* __restrict__ W1x,
      const float* __restrict__ bias, float* __restrict__ gc1)
{
    PIPE_SMEM
    const int tid  = threadIdx.x;
    const int row0 = blockIdx.x * 128;
    const int y    = blockIdx.y;
    const Frag fg  = make_frag(tid);

    float acc[2][8][4];
    pipe_core(acc, aB, bB, h32, nullptr, HH, 128, W1x + (size_t)y * 128 * 128, 128, row0, fg, tid);

    const int ccol0 = y * 128;
    #pragma unroll
    for (int mi = 0; mi < 2; ++mi) {
        const int rbase = row0 + fg.wm * 32 + mi * 16 + fg.gr;
        #pragma unroll
        for (int ni = 0; ni < 8; ++ni) {
            const int cc = ccol0 + fg.wn * 64 + ni * 8 + fg.gc * 2;
            #pragma unroll
            for (int hh = 0; hh < 2; ++hh) {
                int r = rbase + hh * 8;
                if (r < NN) {
                    float v0 = acc[mi][ni][hh * 2 + 0] + bias[cc];
                    float v1 = acc[mi][ni][hh * 2 + 1] + bias[cc + 1];
                    *reinterpret_cast<float2*>(gc1 + (size_t)r * 384 + cc) = make_float2(v0, v1);
                }
            }
        }
    }
}

// ---------------------------------------------------------------------------
// k_hn: hn = h32@Whn; fused GRU: h = (1-z)*tanh(xn + r*hn) + z*h; h32 = tf32(h)
// ---------------------------------------------------------------------------
__global__ void __launch_bounds__(256)
k_hn(const float* __restrict__ hin, const float* __restrict__ h32in,
     const float* __restrict__ Whn, const float* __restrict__ bhn,
     const float* __restrict__ gates,
     float* __restrict__ hout, float* __restrict__ h32out)
{
    PIPE_SMEM
    const int tid  = threadIdx.x;
    const int row0 = blockIdx.x * 128;
    const Frag fg  = make_frag(tid);

    float acc[2][8][4];
    pipe_core(acc, aB, bB, h32in, nullptr, HH, 128, Whn, 128, row0, fg, tid);

    #pragma unroll
    for (int mi = 0; mi < 2; ++mi) {
        const int rbase = row0 + fg.wm * 32 + mi * 16 + fg.gr;
        #pragma unroll
        for (int ni = 0; ni < 8; ++ni) {
            const int cc = fg.wn * 64 + ni * 8 + fg.gc * 2;
            #pragma unroll
            for (int hh = 0; hh < 2; ++hh) {
                int r = rbase + hh * 8;
                if (r < NN) {
                    float hn0 = acc[mi][ni][hh * 2 + 0] + bhn[cc];
                    float hn1 = acc[mi][ni][hh * 2 + 1] + bhn[cc + 1];
                    const float* g = gates + (size_t)r * 384;
                    float2 rv = *reinterpret_cast<const float2*>(g + cc);
                    float2 zv = *reinterpret_cast<const float2*>(g + 128 + cc);
                    float2 xn = *reinterpret_cast<const float2*>(g + 256 + cc);
                    float2 hv = *reinterpret_cast<const float2*>(hin + (size_t)r * HH + cc);
                    float r0 = 1.0f / (1.0f + expf(-rv.x));
                    float r1 = 1.0f / (1.0f + expf(-rv.y));
                    float z0 = 1.0f / (1.0f + expf(-zv.x));
                    float z1 = 1.0f / (1.0f + expf(-zv.y));
                    float n0 = tanhf(xn.x + r0 * hn0);
                    float n1 = tanhf(xn.y + r1 * hn1);
                    float o0 = (1.0f - z0) * n0 + z0 * hv.x;
                    float o1 = (1.0f - z1) * n1 + z1 * hv.y;
                    *reinterpret_cast<float2*>(hout + (size_t)r * HH + cc) = make_float2(o0, o1);
                    *reinterpret_cast<float2*>(h32out + (size_t)r * HH + cc) =
                        make_float2(to_tf32(o0), to_tf32(o1));
                }
            }
        }
    }
}

// ---------------------------------------------------------------------------
// Launch
// ---------------------------------------------------------------------------
extern "C" void kernel_launch(void* const* d_in, const int* in_sizes, int n_in,
                              void* d_out, int out_size)
{
    const float* x        = (const float*)d_in[0];
    const int*   edges    = (const int*)  d_in[1];
    const float* msg_W    = (const float*)d_in[2];
    const float* msg_b    = (const float*)d_in[3];
    const float* g0_Wih   = (const float*)d_in[4];
    const float* g0_Whh   = (const float*)d_in[5];
    const float* g0_bih   = (const float*)d_in[6];
    const float* g0_bhh   = (const float*)d_in[7];
    const float* g1_Wih   = (const float*)d_in[8];
    const float* g1_Whh   = (const float*)d_in[9];
    const float* g1_bih   = (const float*)d_in[10];
    const float* g1_bhh   = (const float*)d_in[11];

    float *h_, *h32_, *S_, *inc_, *gates_, *gc1_, *Wcat_, *Wrz0_, *Wrz1_;
    float *W1x_, *Wxn0_, *Wxn1_, *Whn0_, *Whn1_, *b0cat_, *b1cat_;
    int *cnt_, *off_, *cur_;
    cudaGetSymbolAddress((void**)&h_,     g_h);
    cudaGetSymbolAddress((void**)&h32_,   g_h32);
    cudaGetSymbolAddress((void**)&S_,     g_S);
    cudaGetSymbolAddress((void**)&inc_,   g_inc);
    cudaGetSymbolAddress((void**)&gates_, g_gates);
    cudaGetSymbolAddress((void**)&gc1_,   g_gc1);
    cudaGetSymbolAddress((void**)&Wcat_,  g_Wcat);
    cudaGetSymbolAddress((void**)&Wrz0_,  g_Wrz0);
    cudaGetSymbolAddress((void**)&Wrz1_,  g_Wrz1);
    cudaGetSymbolAddress((void**)&W1x_,   g_W1x);
    cudaGetSymbolAddress((void**)&Wxn0_,  g_Wxn0);
    cudaGetSymbolAddress((void**)&Wxn1_,  g_Wxn1);
    cudaGetSymbolAddress((void**)&Whn0_,  g_Whn0);
    cudaGetSymbolAddress((void**)&Whn1_,  g_Whn1);
    cudaGetSymbolAddress((void**)&b0cat_, g_b0cat);
    cudaGetSymbolAddress((void**)&b1cat_, g_b1cat);
    cudaGetSymbolAddress((void**)&cnt_,   g_cnt);
    cudaGetSymbolAddress((void**)&off_,   g_off);
    cudaGetSymbolAddress((void**)&cur_,   g_cur);

    const size_t hbytes = (size_t)NN * HH * sizeof(float);

    cudaMemcpyAsync(h_, x, hbytes, cudaMemcpyDeviceToDevice);

    // --- CSR build ---
    cudaMemsetAsync(cnt_, 0, SEGS * sizeof(int));
    count_kernel<<<(TT*EE + 255)/256, 256>>>(edges);
    scan_kernel<<<1, 1024>>>();
    cudaMemcpyAsync(cur_, off_, SEGS * sizeof(int), cudaMemcpyDeviceToDevice);
    fill_kernel<<<(TT*EE + 255)/256, 256>>>(edges);

    // --- Weight prep (all GEMM operands pre-rounded to tf32) ---
    wcat_kernel<<<(2*HH*K4 + 255)/256, 256>>>(msg_W);
    build_prep<<<(246528 + 255)/256, 256>>>(g0_Wih, g0_Whh, g0_bih, g0_bhh,
                                            g1_Wih, g1_Whh, g1_bih, g1_bhh);
    round_kernel<<<(NN*HH + 255)/256, 256>>>(x, h32_);

    const int  nblk = (NN + 127)/128;   // 391
    const dim3 g3(nblk, 3);

    // gc1 = x-part of layer1 gates (constant across layer-1 steps)
    k_pre<<<g3, 256>>>(h32_, W1x_, b1cat_, gc1_);

    for (int l = 0; l < 2; ++l) {
        const float* Wc  = Wcat_ + (size_t)l * HH * K4;
        const float* bl  = msg_b + (size_t)l * TT * HH;
        const float* Wrz = l ? Wrz1_ : Wrz0_;
        const float* Wxn = l ? Wxn1_ : Wxn0_;
        const float* Whn = l ? Whn1_ : Whn0_;
        const float* bhn = (l ? g1_bhh : g0_bhh) + 256;
        const float* bias = l ? nullptr : b0cat_;
        const float* cin  = l ? gc1_ : nullptr;
        for (int s = 0; s < 3; ++s) {
            agg_kernel<<<NN, HH>>>(h_);
            k_inc<<<nblk, 256>>>(S_, Wc, bl, inc_);
            k_gates<<<g3, 256>>>(inc_, h32_, Wrz, Wxn, bias, cin, gates_);
            k_hn<<<nblk, 256>>>(h_, h32_, Whn, bhn, gates_, h_, h32_);
        }
    }

    cudaMemcpyAsync(d_out, h_, hbytes, cudaMemcpyDeviceToDevice);
}